// round 11
// baseline (speedup 1.0000x reference)
#include <cuda_runtime.h>
#include <cuda_fp16.h>
#include <math.h>
#include <stdint.h>

#define D 128
#define R 16
#define NCOL 2176
#define MPAD 50048         // 391 * 128
#define NMAX 50000
#define EMAX 800000

// ---------------- scratch (device globals; allocation-free) ----------------
__device__ __half g_trans16[(size_t)MPAD * 2048];  // 204 MB, relation messages
__device__ float g_self[(size_t)MPAD * 128];
__device__ __half g_Ah[(size_t)MPAD * 128];
__device__ __half g_Al[(size_t)MPAD * 128];
__device__ __half g_Bh2[2][NCOL * 128];             // both layers packed upfront
__device__ float g_WT[2][384 * 512];
__device__ float g_gx[2 * 256 * 4 * 512];           // precomputed x-gates [dir][p*4+t][512]
__device__ float g_h[2 * 256 * 128];
// CSR
__device__ int g_cnt[NMAX];
__device__ int g_off[NMAX + 1];
__device__ int g_cur[NMAX];
__device__ uint32_t g_sed[EMAX];   // packed src | (r<<16)

// ---------------- bit-cast helpers ----------------
__device__ __forceinline__ uint32_t h2_as_u32(__half2 h) {
    uint32_t u; *(__half2*)&u = h; return u;
}
__device__ __forceinline__ __half2 u32_as_h2(uint32_t u) {
    __half2 h; *(uint32_t*)&h = u; return h;
}

// ---------------- PTX helpers ----------------
__device__ __forceinline__ uint32_t smem_u32(const void* p) {
    return (uint32_t)__cvta_generic_to_shared(p);
}
__device__ __forceinline__ void ldm_x4(uint32_t& r0, uint32_t& r1, uint32_t& r2, uint32_t& r3,
                                       uint32_t a) {
    asm volatile("ldmatrix.sync.aligned.m8n8.x4.shared.b16 {%0,%1,%2,%3}, [%4];"
                 : "=r"(r0), "=r"(r1), "=r"(r2), "=r"(r3) : "r"(a));
}
__device__ __forceinline__ void ldm_x2(uint32_t& r0, uint32_t& r1, uint32_t a) {
    asm volatile("ldmatrix.sync.aligned.m8n8.x2.shared.b16 {%0,%1}, [%2];"
                 : "=r"(r0), "=r"(r1) : "r"(a));
}
__device__ __forceinline__ void mma16816(float* c, uint32_t a0, uint32_t a1, uint32_t a2,
                                         uint32_t a3, uint32_t b0, uint32_t b1) {
    asm volatile(
        "mma.sync.aligned.m16n8k16.row.col.f32.f16.f16.f32 "
        "{%0,%1,%2,%3}, {%4,%5,%6,%7}, {%8,%9}, {%0,%1,%2,%3};"
        : "+f"(c[0]), "+f"(c[1]), "+f"(c[2]), "+f"(c[3])
        : "r"(a0), "r"(a1), "r"(a2), "r"(a3), "r"(b0), "r"(b1));
}
__device__ __forceinline__ void cpa16(uint32_t dst, const void* src) {
    asm volatile("cp.async.cg.shared.global [%0], [%1], 16;" :: "r"(dst), "l"(src));
}

// ---------------- CSR build ----------------
__global__ void k_zero_cnt(int N) {
    int i = blockIdx.x * blockDim.x + threadIdx.x;
    if (i < N) g_cnt[i] = 0;
}
__global__ void k_hist(const int* __restrict__ dst, int E) {
    int e = blockIdx.x * blockDim.x + threadIdx.x;
    if (e < E) atomicAdd(&g_cnt[dst[e]], 1);
}
__global__ __launch_bounds__(1024) void k_scan(int N) {
    __shared__ int sh[1024];
    int t = threadIdx.x;
    int chunk = (N + 1023) / 1024;
    int c0 = t * chunk, c1 = min(c0 + chunk, N);
    int s = 0;
    for (int i = c0; i < c1; i++) s += g_cnt[i];
    sh[t] = s;
    __syncthreads();
    for (int o = 1; o < 1024; o <<= 1) {
        int v = (t >= o) ? sh[t - o] : 0;
        __syncthreads();
        sh[t] += v;
        __syncthreads();
    }
    int run = sh[t] - s;
    for (int i = c0; i < c1; i++) {
        g_off[i] = run;
        g_cur[i] = run;
        run += g_cnt[i];
    }
    if (t == 1023) g_off[N] = run;
}
__global__ void k_place(const int* __restrict__ src, const int* __restrict__ dst,
                        const int* __restrict__ et, int E) {
    int e = blockIdx.x * blockDim.x + threadIdx.x;
    if (e >= E) return;
    int pos = atomicAdd(&g_cur[dst[e]], 1);
    g_sed[pos] = (uint32_t)src[e] | ((uint32_t)et[e] << 16);
}

// ---------------- conversions ----------------
__global__ void k_conv(const float* __restrict__ x0, int Nn) {
    int i4 = blockIdx.x * blockDim.x + threadIdx.x;
    if (i4 >= MPAD * 32) return;
    int row = i4 >> 5;
    float4 v = make_float4(0.f, 0.f, 0.f, 0.f);
    if (row < Nn) v = *(const float4*)(x0 + (size_t)i4 * 4);
    __half2 h0 = __floats2half2_rn(v.x, v.y);
    __half2 h1 = __floats2half2_rn(v.z, v.w);
    float2 f0 = __half22float2(h0), f1 = __half22float2(h1);
    __half2 l0 = __floats2half2_rn(v.x - f0.x, v.y - f0.y);
    __half2 l1 = __floats2half2_rn(v.z - f1.x, v.w - f1.y);
    ((uint2*)g_Ah)[i4] = make_uint2(h2_as_u32(h0), h2_as_u32(h1));
    ((uint2*)g_Al)[i4] = make_uint2(h2_as_u32(l0), h2_as_u32(l1));
}

__global__ void k_packb(const float* __restrict__ Wrel, const float* __restrict__ Wself) {
    int idx0 = blockIdx.x * blockDim.x + threadIdx.x;
    if (idx0 >= 2 * NCOL * 128) return;
    int l = idx0 / (NCOL * 128);
    int idx = idx0 % (NCOL * 128);
    int n = idx >> 7, d = idx & 127;
    const float* Wr = Wrel + (size_t)l * R * 128 * 128;
    const float* Ws = Wself + (size_t)l * 128 * 128;
    float v;
    if (n < 2048) {
        int r = n >> 7, k = n & 127;
        v = Wr[((size_t)r * 128 + d) * 128 + k];
    } else {
        v = Ws[d * 128 + (n - 2048)];
    }
    g_Bh2[l][idx] = __float2half_rn(v);
}

// ---------------- A-resident pipelined GEMM: 64-row m-tiles, 2 CTAs/SM ----------------
#define SM_AH 0
#define SM_AL 16384
#define SM_B0 32768
#define SM_B1 65536
#define GSMEM 98304

__device__ __forceinline__ void prefetch_a(uint32_t sbase, const __half* Ah, const __half* Al,
                                           int m0, int t) {
#pragma unroll
    for (int it = 0; it < 4; it++) {
        int cl = it * 256 + t;                 // 1024 chunks: 64 rows x 16
        int row = cl >> 4, c = cl & 15;
        uint32_t soff = row * 256 + ((c ^ (row & 7)) * 16);
        cpa16(sbase + SM_AH + soff, Ah + (size_t)(m0 + row) * 128 + c * 8);
        cpa16(sbase + SM_AL + soff, Al + (size_t)(m0 + row) * 128 + c * 8);
    }
    asm volatile("cp.async.commit_group;");
}

__device__ __forceinline__ void prefetch_b(uint32_t dstb, const __half* gsrc, int t) {
#pragma unroll
    for (int it = 0; it < 8; it++) {
        int cl = it * 256 + t;                 // 2048 chunks: 128 rows x 16
        int row = cl >> 4, c = cl & 15;
        cpa16(dstb + row * 256 + ((c ^ (row & 7)) * 16), gsrc + (size_t)row * 128 + c * 8);
    }
    asm volatile("cp.async.commit_group;");
}

__global__ __launch_bounds__(256, 2) void k_gemm(int layer) {
    extern __shared__ char smem[];
    int t = threadIdx.x, lane = t & 31, w = t >> 5;
    int m0 = blockIdx.x * 64;
    uint32_t sbase = smem_u32(smem);
    const __half* Bh = g_Bh2[layer];

    prefetch_b(sbase + SM_B0, Bh, t);
    prefetch_a(sbase, g_Ah, g_Al, m0, t);

    int wm = (w & 1) * 32, wn = (w >> 1) * 32;
    int atile = lane >> 3, ar = lane & 7;
    int arow_base = wm + ((atile & 1) << 3) + ar;     // + i*16
    int achunk_sel = atile >> 1;
    int bl = lane & 15;
    int bhalf = bl >> 3, br = bl & 7;

    for (int n = 0; n < 17; n++) {
        uint32_t boff = (n & 1) ? SM_B1 : SM_B0;
        uint32_t bbase = sbase + boff;
        asm volatile("cp.async.wait_group 0;");
        __syncthreads();
        if (n + 1 < 17) {
            prefetch_b(sbase + (((n + 1) & 1) ? SM_B1 : SM_B0),
                       Bh + (size_t)(n + 1) * 128 * 128, t);
        }

        float acc[2][4][4];
#pragma unroll
        for (int i = 0; i < 2; i++)
#pragma unroll
            for (int j = 0; j < 4; j++)
#pragma unroll
                for (int q = 0; q < 4; q++) acc[i][j][q] = 0.0f;

#pragma unroll
        for (int pass = 0; pass < 2; pass++) {
            uint32_t abase = sbase + (pass ? SM_AL : SM_AH);
#pragma unroll
            for (int ks = 0; ks < 8; ks++) {
                uint32_t a[2][4];
                uint32_t b[4][2];
                int ac = ks * 2 + achunk_sel;
#pragma unroll
                for (int i = 0; i < 2; i++) {
                    int row = arow_base + i * 16;
                    ldm_x4(a[i][0], a[i][1], a[i][2], a[i][3],
                           abase + row * 256 + ((ac ^ (row & 7)) * 16));
                }
                int bc = ks * 2 + bhalf;
#pragma unroll
                for (int j = 0; j < 4; j++) {
                    int row = wn + j * 8 + br;
                    ldm_x2(b[j][0], b[j][1], bbase + row * 256 + ((bc ^ (row & 7)) * 16));
                }
#pragma unroll
                for (int i = 0; i < 2; i++)
#pragma unroll
                    for (int j = 0; j < 4; j++)
                        mma16816(acc[i][j], a[i][0], a[i][1], a[i][2], a[i][3], b[j][0], b[j][1]);
            }
        }
        __syncthreads();   // all warps done reading this B buffer

        if (n < 16) {
            // stage fp16 C into the just-consumed B buffer (64 x 136 halves = 17.4KB)
            __half* cs = (__half*)(smem + boff);
#pragma unroll
            for (int i = 0; i < 2; i++) {
#pragma unroll
                for (int j = 0; j < 4; j++) {
                    int r = wm + i * 16 + (lane >> 2);
                    int c = wn + j * 8 + 2 * (lane & 3);
                    *(__half2*)(cs + r * 136 + c) = __floats2half2_rn(acc[i][j][0], acc[i][j][1]);
                    *(__half2*)(cs + (r + 8) * 136 + c) = __floats2half2_rn(acc[i][j][2], acc[i][j][3]);
                }
            }
            __syncthreads();
#pragma unroll
            for (int it = 0; it < 4; it++) {
                int idx = it * 256 + t;            // 1024 chunks: 64 rows x 16 x 16B
                int row = idx >> 4, ch = idx & 15;
                uint4 v = *(const uint4*)(cs + row * 136 + ch * 8);
                *(uint4*)(g_trans16 + (size_t)(m0 + row) * 2048 + n * 128 + ch * 8) = v;
            }
        } else {
            // self block fp32: two 32-row staging rounds (32 x 136 floats = 17.4KB)
            float* cs = (float*)(smem + boff);
#pragma unroll
            for (int h = 0; h < 2; h++) {
                if ((w & 1) == h) {
#pragma unroll
                    for (int i = 0; i < 2; i++) {
#pragma unroll
                        for (int j = 0; j < 4; j++) {
                            int r = i * 16 + (lane >> 2);   // local row in 0..31
                            int c = wn + j * 8 + 2 * (lane & 3);
                            *(float2*)(cs + r * 136 + c) = make_float2(acc[i][j][0], acc[i][j][1]);
                            *(float2*)(cs + (r + 8) * 136 + c) = make_float2(acc[i][j][2], acc[i][j][3]);
                        }
                    }
                }
                __syncthreads();
#pragma unroll
                for (int it = 0; it < 4; it++) {
                    int idx = it * 256 + t;        // 1024 chunks: 32 rows x 32 float4
                    int row = idx >> 5, c4 = (idx & 31) * 4;
                    float4 v = *(const float4*)(cs + row * 136 + c4);
                    *(float4*)(g_self + (size_t)(m0 + h * 32 + row) * 128 + c4) = v;
                }
                __syncthreads();
            }
        }
    }
}

// ---------------- fused gather + update: warp per node, half-warp per edge ----------------
__device__ __forceinline__ void acc8(float* a, uint4 r) {
    float2 f;
    f = __half22float2(u32_as_h2(r.x)); a[0] += f.x; a[1] += f.y;
    f = __half22float2(u32_as_h2(r.y)); a[2] += f.x; a[3] += f.y;
    f = __half22float2(u32_as_h2(r.z)); a[4] += f.x; a[5] += f.y;
    f = __half22float2(u32_as_h2(r.w)); a[6] += f.x; a[7] += f.y;
}
__device__ __forceinline__ uint4 ldg_msg(const __half* p) {
    return __ldg((const uint4*)p);
}

__global__ __launch_bounds__(256) void k_gather(const float* __restrict__ bself,
                                                const float* __restrict__ lg,
                                                const float* __restrict__ lb,
                                                float* __restrict__ enc_out,
                                                int layer, int M) {
    int n = blockIdx.x * 8 + (threadIdx.x >> 5);
    int lane = threadIdx.x & 31;
    if (n >= M) return;
    int half = lane >> 4, hl = lane & 15;
    int beg = g_off[n], end = g_off[n + 1];

    float acc[8];
#pragma unroll
    for (int q = 0; q < 8; q++) acc[q] = 0.0f;

    int e = beg + half;
    for (; e + 6 < end; e += 8) {
        uint32_t p0 = g_sed[e], p1 = g_sed[e + 2], p2 = g_sed[e + 4], p3 = g_sed[e + 6];
        uint4 r0 = ldg_msg(g_trans16 + (size_t)(p0 & 0xFFFF) * 2048 + ((p0 >> 16) << 7) + hl * 8);
        uint4 r1 = ldg_msg(g_trans16 + (size_t)(p1 & 0xFFFF) * 2048 + ((p1 >> 16) << 7) + hl * 8);
        uint4 r2 = ldg_msg(g_trans16 + (size_t)(p2 & 0xFFFF) * 2048 + ((p2 >> 16) << 7) + hl * 8);
        uint4 r3 = ldg_msg(g_trans16 + (size_t)(p3 & 0xFFFF) * 2048 + ((p3 >> 16) << 7) + hl * 8);
        acc8(acc, r0); acc8(acc, r1); acc8(acc, r2); acc8(acc, r3);
    }
    for (; e < end; e += 2) {
        uint32_t p = g_sed[e];
        uint4 r = ldg_msg(g_trans16 + (size_t)(p & 0xFFFF) * 2048 + ((p >> 16) << 7) + hl * 8);
        acc8(acc, r);
    }
#pragma unroll
    for (int q = 0; q < 8; q++) acc[q] += __shfl_xor_sync(0xFFFFFFFFu, acc[q], 16);

    float inv = 1.0f / fmaxf((float)(end - beg), 1.0f);
    float4 s0 = *(const float4*)(g_self + (size_t)n * 128 + hl * 8);
    float4 s1 = *(const float4*)(g_self + (size_t)n * 128 + hl * 8 + 4);
    float4 b0 = *(const float4*)(bself + hl * 8);
    float4 b1 = *(const float4*)(bself + hl * 8 + 4);
    float v[8];
    v[0] = fmaxf(s0.x + b0.x + acc[0] * inv, 0.f);
    v[1] = fmaxf(s0.y + b0.y + acc[1] * inv, 0.f);
    v[2] = fmaxf(s0.z + b0.z + acc[2] * inv, 0.f);
    v[3] = fmaxf(s0.w + b0.w + acc[3] * inv, 0.f);
    v[4] = fmaxf(s1.x + b1.x + acc[4] * inv, 0.f);
    v[5] = fmaxf(s1.y + b1.y + acc[5] * inv, 0.f);
    v[6] = fmaxf(s1.z + b1.z + acc[6] * inv, 0.f);
    v[7] = fmaxf(s1.w + b1.w + acc[7] * inv, 0.f);

    float s = 0.f;
#pragma unroll
    for (int q = 0; q < 8; q++) s += v[q];
#pragma unroll
    for (int o = 1; o < 16; o <<= 1) s += __shfl_xor_sync(0xFFFFFFFFu, s, o);
    float mu = s * (1.0f / 128.0f);
    float qs = 0.f;
    float dv[8];
#pragma unroll
    for (int q = 0; q < 8; q++) { dv[q] = v[q] - mu; qs += dv[q] * dv[q]; }
#pragma unroll
    for (int o = 1; o < 16; o <<= 1) qs += __shfl_xor_sync(0xFFFFFFFFu, qs, o);
    float rstd = rsqrtf(qs * (1.0f / 128.0f) + 1e-5f);

    float4 g0 = *(const float4*)(lg + hl * 8);
    float4 g1 = *(const float4*)(lg + hl * 8 + 4);
    float4 p0 = *(const float4*)(lb + hl * 8);
    float4 p1 = *(const float4*)(lb + hl * 8 + 4);
    float ov[8];
    ov[0] = dv[0] * rstd * g0.x + p0.x; ov[1] = dv[1] * rstd * g0.y + p0.y;
    ov[2] = dv[2] * rstd * g0.z + p0.z; ov[3] = dv[3] * rstd * g0.w + p0.w;
    ov[4] = dv[4] * rstd * g1.x + p1.x; ov[5] = dv[5] * rstd * g1.y + p1.y;
    ov[6] = dv[6] * rstd * g1.z + p1.z; ov[7] = dv[7] * rstd * g1.w + p1.w;

    if (half == 0) {
        if (layer == 0) {
            __half2 h0 = __floats2half2_rn(ov[0], ov[1]);
            __half2 h1 = __floats2half2_rn(ov[2], ov[3]);
            __half2 h2 = __floats2half2_rn(ov[4], ov[5]);
            __half2 h3 = __floats2half2_rn(ov[6], ov[7]);
            float2 f0 = __half22float2(h0), f1 = __half22float2(h1);
            float2 f2 = __half22float2(h2), f3 = __half22float2(h3);
            __half2 l0 = __floats2half2_rn(ov[0] - f0.x, ov[1] - f0.y);
            __half2 l1 = __floats2half2_rn(ov[2] - f1.x, ov[3] - f1.y);
            __half2 l2 = __floats2half2_rn(ov[4] - f2.x, ov[5] - f2.y);
            __half2 l3 = __floats2half2_rn(ov[6] - f3.x, ov[7] - f3.y);
            *(uint4*)(g_Ah + (size_t)n * 128 + hl * 8) =
                make_uint4(h2_as_u32(h0), h2_as_u32(h1), h2_as_u32(h2), h2_as_u32(h3));
            *(uint4*)(g_Al + (size_t)n * 128 + hl * 8) =
                make_uint4(h2_as_u32(l0), h2_as_u32(l1), h2_as_u32(l2), h2_as_u32(l3));
        } else {
            *(float4*)(enc_out + (size_t)n * 128 + hl * 8) =
                make_float4(ov[0], ov[1], ov[2], ov[3]);
            *(float4*)(enc_out + (size_t)n * 128 + hl * 8 + 4) =
                make_float4(ov[4], ov[5], ov[6], ov[7]);
        }
    }
}

__global__ void k_wt(const float* __restrict__ Wih_f, const float* __restrict__ Whh_f,
                     const float* __restrict__ Wih_b, const float* __restrict__ Whh_b) {
    int idx = blockIdx.x * blockDim.x + threadIdx.x;
    if (idx >= 2 * 384 * 512) return;
    int dir = idx / (384 * 512);
    int rem = idx % (384 * 512);
    int d = rem / 512, j = rem % 512;
    const float* Wih = dir ? Wih_b : Wih_f;
    const float* Whh = dir ? Whh_b : Whh_f;
    float v = (d < 256) ? Wih[j * 256 + d] : Whh[j * 128 + (d - 256)];
    g_WT[dir][rem] = v;
}

// ---------------- LSTM input projection (seq build fused in) ----------------
__global__ __launch_bounds__(512) void k_xgate(const float* __restrict__ enc,
                                               const int* __restrict__ pn,
                                               const int* __restrict__ pr,
                                               const float* __restrict__ rel,
                                               const float* __restrict__ bf,
                                               const float* __restrict__ bb) {
    __shared__ float xt[256];
    int pl = blockIdx.x;               // p*4 + t
    int p = pl >> 2, tt = pl & 3;
    int dir = blockIdx.y;
    int j = threadIdx.x;
    const float* WT = g_WT[dir];
    const float* bias = dir ? bb : bf;
    if (j < 128) {
        int node = pn[p * 4 + tt];
        xt[j] = enc[(size_t)node * 128 + j];
    } else if (j < 256) {
        int d = j - 128;
        float rv = 0.0f;
        if (tt > 0) { int r = pr[p * 3 + (tt - 1)]; rv = rel[r * 128 + d]; }
        xt[j] = rv;
    }
    __syncthreads();
    float acc = bias[j];
    for (int d = 0; d < 256; d++) acc = fmaf(WT[d * 512 + j], xt[d], acc);
    g_gx[((size_t)dir * 1024 + pl) * 512 + j] = acc;
}

// ---------------- bidirectional LSTM: recurrent part only (K=128) ----------------
__global__ __launch_bounds__(512) void k_lstm() {
    const int PB = 8;
    __shared__ float hs[PB][128];
    __shared__ float cs[PB][128];
    __shared__ float gs[PB][512];
    int dir = blockIdx.y;
    const float* WT = g_WT[dir];
    int p0 = blockIdx.x * PB;
    int t = threadIdx.x;

    for (int i = t; i < PB * 128; i += 512) { ((float*)hs)[i] = 0.0f; ((float*)cs)[i] = 0.0f; }
    __syncthreads();

    for (int step = 0; step < 4; step++) {
        int tt = dir ? (3 - step) : step;
        float acc[PB];
#pragma unroll
        for (int p = 0; p < PB; p++)
            acc[p] = g_gx[((size_t)dir * 1024 + (p0 + p) * 4 + tt) * 512 + t];
        for (int d = 0; d < 128; d++) {
            float w = WT[(256 + d) * 512 + t];
#pragma unroll
            for (int p = 0; p < PB; p++) acc[p] = fmaf(w, hs[p][d], acc[p]);
        }
#pragma unroll
        for (int p = 0; p < PB; p++) gs[p][t] = acc[p];
        __syncthreads();
        for (int i = t; i < PB * 128; i += 512) {
            int pp = i >> 7, k = i & 127;
            float ig = 1.0f / (1.0f + expf(-gs[pp][k]));
            float fg = 1.0f / (1.0f + expf(-gs[pp][128 + k]));
            float gg = tanhf(gs[pp][256 + k]);
            float og = 1.0f / (1.0f + expf(-gs[pp][384 + k]));
            float c = fg * cs[pp][k] + ig * gg;
            cs[pp][k] = c;
            hs[pp][k] = og * tanhf(c);
        }
        __syncthreads();
    }
    for (int i = t; i < PB * 128; i += 512) {
        int pp = i >> 7, k = i & 127;
        g_h[((size_t)dir * 256 + p0 + pp) * 128 + k] = hs[pp][k];
    }
}

// ---------------- output head ----------------
__global__ void k_head(const float* __restrict__ Wop, const float* __restrict__ bop,
                       const float* __restrict__ q, const float* __restrict__ Ws1,
                       const float* __restrict__ bs1, const float* __restrict__ Ws2,
                       const float* __restrict__ bs2,
                       float* __restrict__ pe_out, float* __restrict__ sim_out) {
    int p = blockIdx.x;
    int k = threadIdx.x;
    __shared__ float cat[256];
    __shared__ float cat2[256];
    __shared__ float red[4];
    cat[k]       = g_h[(size_t)p * 128 + k];
    cat[128 + k] = g_h[(size_t)(256 + p) * 128 + k];
    __syncthreads();
    float acc = bop[k];
    for (int j = 0; j < 256; j++) acc = fmaf(cat[j], Wop[k * 256 + j], acc);
    float pe = fmaxf(acc, 0.0f);
    pe_out[(size_t)p * 128 + k] = pe;
    cat2[k] = pe;
    cat2[128 + k] = q[k];
    __syncthreads();
    float a2 = bs1[k];
    for (int j = 0; j < 256; j++) a2 = fmaf(cat2[j], Ws1[k * 256 + j], a2);
    float hdn = fmaxf(a2, 0.0f);
    float s = hdn * Ws2[k];
#pragma unroll
    for (int o = 16; o > 0; o >>= 1) s += __shfl_xor_sync(0xFFFFFFFFu, s, o);
    if ((k & 31) == 0) red[k >> 5] = s;
    __syncthreads();
    if (k == 0) {
        float tot = red[0] + red[1] + red[2] + red[3] + bs2[0];
        sim_out[p] = 1.0f / (1.0f + expf(-tot));
    }
}

// ---------------- launch ----------------
extern "C" void kernel_launch(void* const* d_in, const int* in_sizes, int n_in,
                              void* d_out, int out_size) {
    const float* node_features = (const float*)d_in[0];
    const int*   edge_index    = (const int*)d_in[1];
    const int*   edge_types    = (const int*)d_in[2];
    const float* query         = (const float*)d_in[3];
    const int*   path_nodes    = (const int*)d_in[4];
    const int*   path_rel      = (const int*)d_in[5];
    const float* W_self        = (const float*)d_in[6];
    const float* b_self        = (const float*)d_in[7];
    const float* W_rel         = (const float*)d_in[8];
    const float* ln_g          = (const float*)d_in[9];
    const float* ln_b          = (const float*)d_in[10];
    const float* rel_emb       = (const float*)d_in[11];
    const float* W_ih_f        = (const float*)d_in[12];
    const float* W_hh_f        = (const float*)d_in[13];
    const float* b_f           = (const float*)d_in[14];
    const float* W_ih_b        = (const float*)d_in[15];
    const float* W_hh_b        = (const float*)d_in[16];
    const float* b_b           = (const float*)d_in[17];
    const float* W_op          = (const float*)d_in[18];
    const float* b_op          = (const float*)d_in[19];
    const float* W_s1          = (const float*)d_in[20];
    const float* b_s1          = (const float*)d_in[21];
    const float* W_s2          = (const float*)d_in[22];
    const float* b_s2          = (const float*)d_in[23];
    (void)n_in; (void)out_size;

    const int N = in_sizes[0] / 128;
    const int E = in_sizes[1] / 2;
    const int P = in_sizes[4] / 4;

    float* out     = (float*)d_out;
    float* enc_out = out;
    float* pe_out  = out + (size_t)N * 128;
    float* sim_out = pe_out + (size_t)P * 128;

    const int* src = edge_index;
    const int* dst = edge_index + E;

    cudaFuncSetAttribute(k_gemm, cudaFuncAttributeMaxDynamicSharedMemorySize, GSMEM);

    // order chosen so k_gemm is the 4th launch (ncu capture slot)
    k_conv<<<(MPAD * 32 + 255) / 256, 256>>>(node_features, N);
    k_packb<<<(2 * NCOL * 128 + 255) / 256, 256>>>(W_rel, W_self);
    k_wt<<<(2 * 384 * 512 + 255) / 256, 256>>>(W_ih_f, W_hh_f, W_ih_b, W_hh_b);
    k_gemm<<<MPAD / 64, 256, GSMEM>>>(0);

    k_zero_cnt<<<(N + 255) / 256, 256>>>(N);
    k_hist<<<(E + 255) / 256, 256>>>(dst, E);
    k_scan<<<1, 1024>>>(N);
    k_place<<<(E + 255) / 256, 256>>>(src, dst, edge_types, E);

    k_gather<<<(N + 7) / 8, 256>>>(b_self, ln_g, ln_b, enc_out, 0, N);
    k_gemm<<<MPAD / 64, 256, GSMEM>>>(1);
    k_gather<<<(N + 7) / 8, 256>>>(b_self + 128, ln_g + 128, ln_b + 128, enc_out, 1, N);

    k_xgate<<<dim3(P * 4, 2), 512>>>(enc_out, path_nodes, path_rel, rel_emb, b_f, b_b);
    k_lstm<<<dim3(P / 8, 2), 512>>>();
    k_head<<<P, 128>>>(W_op, b_op, query, W_s1, b_s1, W_s2, b_s2, pe_out, sim_out);
}

// round 12
// speedup vs baseline: 1.6253x; 1.6253x over previous
#include <cuda_runtime.h>
#include <cuda_fp16.h>
#include <math.h>
#include <stdint.h>

#define D 128
#define R 16
#define NCOL 2176
#define MPAD 50048         // 391 * 128
#define NMAX 50000
#define EMAX 800000

// ---------------- scratch (device globals; allocation-free) ----------------
__device__ __half g_trans16[(size_t)MPAD * 2048];  // 204 MB, relation messages
__device__ float g_self[(size_t)MPAD * 128];
__device__ __half g_Ah[(size_t)MPAD * 128];
__device__ __half g_Al[(size_t)MPAD * 128];
__device__ __half g_Bh2[2][NCOL * 128];             // both layers packed upfront
__device__ float g_WT[2][384 * 512];
__device__ float g_gx[2 * 256 * 4 * 512];           // precomputed x-gates [dir][p*4+t][512]
__device__ float g_h[2 * 256 * 128];
// CSR
__device__ int g_cnt[NMAX];
__device__ int g_off[NMAX + 1];
__device__ int g_cur[NMAX];
__device__ uint32_t g_sed[EMAX];   // packed src | (r<<16)

// ---------------- bit-cast helpers ----------------
__device__ __forceinline__ uint32_t h2_as_u32(__half2 h) {
    uint32_t u; *(__half2*)&u = h; return u;
}
__device__ __forceinline__ __half2 u32_as_h2(uint32_t u) {
    __half2 h; *(uint32_t*)&h = u; return h;
}

// ---------------- PTX helpers ----------------
__device__ __forceinline__ uint32_t smem_u32(const void* p) {
    return (uint32_t)__cvta_generic_to_shared(p);
}
__device__ __forceinline__ void ldm_x4(uint32_t& r0, uint32_t& r1, uint32_t& r2, uint32_t& r3,
                                       uint32_t a) {
    asm volatile("ldmatrix.sync.aligned.m8n8.x4.shared.b16 {%0,%1,%2,%3}, [%4];"
                 : "=r"(r0), "=r"(r1), "=r"(r2), "=r"(r3) : "r"(a));
}
__device__ __forceinline__ void ldm_x2(uint32_t& r0, uint32_t& r1, uint32_t a) {
    asm volatile("ldmatrix.sync.aligned.m8n8.x2.shared.b16 {%0,%1}, [%2];"
                 : "=r"(r0), "=r"(r1) : "r"(a));
}
__device__ __forceinline__ void mma16816(float* c, uint32_t a0, uint32_t a1, uint32_t a2,
                                         uint32_t a3, uint32_t b0, uint32_t b1) {
    asm volatile(
        "mma.sync.aligned.m16n8k16.row.col.f32.f16.f16.f32 "
        "{%0,%1,%2,%3}, {%4,%5,%6,%7}, {%8,%9}, {%0,%1,%2,%3};"
        : "+f"(c[0]), "+f"(c[1]), "+f"(c[2]), "+f"(c[3])
        : "r"(a0), "r"(a1), "r"(a2), "r"(a3), "r"(b0), "r"(b1));
}
__device__ __forceinline__ void cpa16(uint32_t dst, const void* src) {
    asm volatile("cp.async.cg.shared.global [%0], [%1], 16;" :: "r"(dst), "l"(src));
}

// ---------------- CSR build ----------------
__global__ void k_zero_cnt(int N) {
    int i = blockIdx.x * blockDim.x + threadIdx.x;
    if (i < N) g_cnt[i] = 0;
}
__global__ void k_hist(const int* __restrict__ dst, int E) {
    int e = blockIdx.x * blockDim.x + threadIdx.x;
    if (e < E) atomicAdd(&g_cnt[dst[e]], 1);
}
__global__ __launch_bounds__(1024) void k_scan(int N) {
    __shared__ int sh[1024];
    int t = threadIdx.x;
    int chunk = (N + 1023) / 1024;
    int c0 = t * chunk, c1 = min(c0 + chunk, N);
    int s = 0;
    for (int i = c0; i < c1; i++) s += g_cnt[i];
    sh[t] = s;
    __syncthreads();
    for (int o = 1; o < 1024; o <<= 1) {
        int v = (t >= o) ? sh[t - o] : 0;
        __syncthreads();
        sh[t] += v;
        __syncthreads();
    }
    int run = sh[t] - s;
    for (int i = c0; i < c1; i++) {
        g_off[i] = run;
        g_cur[i] = run;
        run += g_cnt[i];
    }
    if (t == 1023) g_off[N] = run;
}
__global__ void k_place(const int* __restrict__ src, const int* __restrict__ dst,
                        const int* __restrict__ et, int E) {
    int e = blockIdx.x * blockDim.x + threadIdx.x;
    if (e >= E) return;
    int pos = atomicAdd(&g_cur[dst[e]], 1);
    g_sed[pos] = (uint32_t)src[e] | ((uint32_t)et[e] << 16);
}

// ---------------- conversions ----------------
__global__ void k_conv(const float* __restrict__ x0, int Nn) {
    int i4 = blockIdx.x * blockDim.x + threadIdx.x;
    if (i4 >= MPAD * 32) return;
    int row = i4 >> 5;
    float4 v = make_float4(0.f, 0.f, 0.f, 0.f);
    if (row < Nn) v = *(const float4*)(x0 + (size_t)i4 * 4);
    __half2 h0 = __floats2half2_rn(v.x, v.y);
    __half2 h1 = __floats2half2_rn(v.z, v.w);
    float2 f0 = __half22float2(h0), f1 = __half22float2(h1);
    __half2 l0 = __floats2half2_rn(v.x - f0.x, v.y - f0.y);
    __half2 l1 = __floats2half2_rn(v.z - f1.x, v.w - f1.y);
    ((uint2*)g_Ah)[i4] = make_uint2(h2_as_u32(h0), h2_as_u32(h1));
    ((uint2*)g_Al)[i4] = make_uint2(h2_as_u32(l0), h2_as_u32(l1));
}

__global__ void k_packb(const float* __restrict__ Wrel, const float* __restrict__ Wself) {
    int idx0 = blockIdx.x * blockDim.x + threadIdx.x;
    if (idx0 >= 2 * NCOL * 128) return;
    int l = idx0 / (NCOL * 128);
    int idx = idx0 % (NCOL * 128);
    int n = idx >> 7, d = idx & 127;
    const float* Wr = Wrel + (size_t)l * R * 128 * 128;
    const float* Ws = Wself + (size_t)l * 128 * 128;
    float v;
    if (n < 2048) {
        int r = n >> 7, k = n & 127;
        v = Wr[((size_t)r * 128 + d) * 128 + k];
    } else {
        v = Ws[d * 128 + (n - 2048)];
    }
    g_Bh2[l][idx] = __float2half_rn(v);
}

// ---------------- A-resident pipelined GEMM: 128-row tiles, 1 CTA/SM ----------------
// Message n-tiles (0..15): single pass Ah*Bh. Self tile (16): Ah*Bh + Al*Bh.
#define SM_AH 0
#define SM_AL 32768
#define SM_B0 65536
#define SM_B1 98304
#define SM_C  131072
#define GSMEM (131072 + 69632)

__device__ __forceinline__ void load_tile(char* dstbase, const __half* g, int row0, int t) {
#pragma unroll
    for (int it = 0; it < 8; it++) {
        int cl = it * 256 + t;
        int row = cl >> 4, c = cl & 15;
        uint4 v = *(const uint4*)(g + (size_t)(row0 + row) * 128 + c * 8);
        *(uint4*)(dstbase + row * 256 + ((c ^ (row & 7)) * 16)) = v;
    }
}

__device__ __forceinline__ void prefetch_b(uint32_t dstb, const __half* gsrc, int t) {
#pragma unroll
    for (int it = 0; it < 8; it++) {
        int cl = it * 256 + t;
        int row = cl >> 4, c = cl & 15;
        cpa16(dstb + row * 256 + ((c ^ (row & 7)) * 16), gsrc + (size_t)row * 128 + c * 8);
    }
    asm volatile("cp.async.commit_group;");
}

__global__ __launch_bounds__(256, 1) void k_gemm(int layer) {
    extern __shared__ char smem[];
    int t = threadIdx.x, lane = t & 31, w = t >> 5;
    int m0 = blockIdx.x * 128;
    uint32_t sbase = smem_u32(smem);
    const __half* Bh = g_Bh2[layer];

    prefetch_b(sbase + SM_B0, Bh, t);
    load_tile(smem + SM_AH, g_Ah, m0, t);
    load_tile(smem + SM_AL, g_Al, m0, t);

    int wm = (w & 1) * 64, wn = (w >> 1) * 32;
    int atile = lane >> 3, ar = lane & 7;
    int arow_base = wm + ((atile & 1) << 3) + ar;
    int achunk_sel = atile >> 1;
    int bl = lane & 15;
    int bhalf = bl >> 3, br = bl & 7;

    for (int n = 0; n < 17; n++) {
        uint32_t bbase = sbase + ((n & 1) ? SM_B1 : SM_B0);
        asm volatile("cp.async.wait_group 0;");
        __syncthreads();
        if (n + 1 < 17) {
            prefetch_b(sbase + (((n + 1) & 1) ? SM_B1 : SM_B0),
                       Bh + (size_t)(n + 1) * 128 * 128, t);
        }

        float acc[4][4][4];
#pragma unroll
        for (int i = 0; i < 4; i++)
#pragma unroll
            for (int j = 0; j < 4; j++)
#pragma unroll
                for (int q = 0; q < 4; q++) acc[i][j][q] = 0.0f;

        int npass = (n < 16) ? 1 : 2;
        for (int pass = 0; pass < npass; pass++) {
            uint32_t abase = sbase + (pass ? SM_AL : SM_AH);
#pragma unroll
            for (int ks = 0; ks < 8; ks++) {
                uint32_t a[4][4];
                uint32_t b[4][2];
                int ac = ks * 2 + achunk_sel;
#pragma unroll
                for (int i = 0; i < 4; i++) {
                    int row = arow_base + i * 16;
                    uint32_t addr = abase + row * 256 + ((ac ^ (row & 7)) * 16);
                    ldm_x4(a[i][0], a[i][1], a[i][2], a[i][3], addr);
                }
                int bc = ks * 2 + bhalf;
#pragma unroll
                for (int j = 0; j < 4; j++) {
                    int row = wn + j * 8 + br;
                    uint32_t addr = bbase + row * 256 + ((bc ^ (row & 7)) * 16);
                    ldm_x2(b[j][0], b[j][1], addr);
                }
#pragma unroll
                for (int i = 0; i < 4; i++)
#pragma unroll
                    for (int j = 0; j < 4; j++)
                        mma16816(acc[i][j], a[i][0], a[i][1], a[i][2], a[i][3], b[j][0], b[j][1]);
            }
        }
        __syncthreads();

        float* cs = (float*)(smem + SM_C);
#pragma unroll
        for (int i = 0; i < 4; i++) {
#pragma unroll
            for (int j = 0; j < 4; j++) {
                int r = wm + i * 16 + (lane >> 2);
                int c = wn + j * 8 + 2 * (lane & 3);
                *(float2*)(cs + r * 136 + c) = make_float2(acc[i][j][0], acc[i][j][1]);
                *(float2*)(cs + (r + 8) * 136 + c) = make_float2(acc[i][j][2], acc[i][j][3]);
            }
        }
        __syncthreads();

        if (n < 16) {
#pragma unroll
            for (int it = 0; it < 16; it++) {
                int idx = it * 256 + t;
                int row = idx >> 5, c4 = (idx & 31) * 4;
                float4 v = *(const float4*)(cs + row * 136 + c4);
                __half2 h0 = __floats2half2_rn(v.x, v.y);
                __half2 h1 = __floats2half2_rn(v.z, v.w);
                *(uint2*)(g_trans16 + (size_t)(m0 + row) * 2048 + n * 128 + c4) =
                    make_uint2(h2_as_u32(h0), h2_as_u32(h1));
            }
        } else {
#pragma unroll
            for (int it = 0; it < 16; it++) {
                int idx = it * 256 + t;
                int row = idx >> 5, c4 = (idx & 31) * 4;
                float4 v = *(const float4*)(cs + row * 136 + c4);
                *(float4*)(g_self + (size_t)(m0 + row) * 128 + c4) = v;
            }
        }
    }
}

// ---------------- fused gather + update: warp per node, half-warp per edge ----------------
__device__ __forceinline__ void acc8(float* a, uint4 r) {
    float2 f;
    f = __half22float2(u32_as_h2(r.x)); a[0] += f.x; a[1] += f.y;
    f = __half22float2(u32_as_h2(r.y)); a[2] += f.x; a[3] += f.y;
    f = __half22float2(u32_as_h2(r.z)); a[4] += f.x; a[5] += f.y;
    f = __half22float2(u32_as_h2(r.w)); a[6] += f.x; a[7] += f.y;
}
__device__ __forceinline__ uint4 ldg_msg(const __half* p) {
    return __ldg((const uint4*)p);
}

__global__ __launch_bounds__(256) void k_gather(const float* __restrict__ bself,
                                                const float* __restrict__ lg,
                                                const float* __restrict__ lb,
                                                float* __restrict__ enc_out,
                                                int layer, int M) {
    int n = blockIdx.x * 8 + (threadIdx.x >> 5);
    int lane = threadIdx.x & 31;
    if (n >= M) return;
    int half = lane >> 4, hl = lane & 15;
    int beg = g_off[n], end = g_off[n + 1];

    float acc[8];
#pragma unroll
    for (int q = 0; q < 8; q++) acc[q] = 0.0f;

    int e = beg + half;
    for (; e + 6 < end; e += 8) {
        uint32_t p0 = g_sed[e], p1 = g_sed[e + 2], p2 = g_sed[e + 4], p3 = g_sed[e + 6];
        uint4 r0 = ldg_msg(g_trans16 + (size_t)(p0 & 0xFFFF) * 2048 + ((p0 >> 16) << 7) + hl * 8);
        uint4 r1 = ldg_msg(g_trans16 + (size_t)(p1 & 0xFFFF) * 2048 + ((p1 >> 16) << 7) + hl * 8);
        uint4 r2 = ldg_msg(g_trans16 + (size_t)(p2 & 0xFFFF) * 2048 + ((p2 >> 16) << 7) + hl * 8);
        uint4 r3 = ldg_msg(g_trans16 + (size_t)(p3 & 0xFFFF) * 2048 + ((p3 >> 16) << 7) + hl * 8);
        acc8(acc, r0); acc8(acc, r1); acc8(acc, r2); acc8(acc, r3);
    }
    for (; e < end; e += 2) {
        uint32_t p = g_sed[e];
        uint4 r = ldg_msg(g_trans16 + (size_t)(p & 0xFFFF) * 2048 + ((p >> 16) << 7) + hl * 8);
        acc8(acc, r);
    }
#pragma unroll
    for (int q = 0; q < 8; q++) acc[q] += __shfl_xor_sync(0xFFFFFFFFu, acc[q], 16);

    float inv = 1.0f / fmaxf((float)(end - beg), 1.0f);
    float4 s0 = *(const float4*)(g_self + (size_t)n * 128 + hl * 8);
    float4 s1 = *(const float4*)(g_self + (size_t)n * 128 + hl * 8 + 4);
    float4 b0 = *(const float4*)(bself + hl * 8);
    float4 b1 = *(const float4*)(bself + hl * 8 + 4);
    float v[8];
    v[0] = fmaxf(s0.x + b0.x + acc[0] * inv, 0.f);
    v[1] = fmaxf(s0.y + b0.y + acc[1] * inv, 0.f);
    v[2] = fmaxf(s0.z + b0.z + acc[2] * inv, 0.f);
    v[3] = fmaxf(s0.w + b0.w + acc[3] * inv, 0.f);
    v[4] = fmaxf(s1.x + b1.x + acc[4] * inv, 0.f);
    v[5] = fmaxf(s1.y + b1.y + acc[5] * inv, 0.f);
    v[6] = fmaxf(s1.z + b1.z + acc[6] * inv, 0.f);
    v[7] = fmaxf(s1.w + b1.w + acc[7] * inv, 0.f);

    float s = 0.f;
#pragma unroll
    for (int q = 0; q < 8; q++) s += v[q];
#pragma unroll
    for (int o = 1; o < 16; o <<= 1) s += __shfl_xor_sync(0xFFFFFFFFu, s, o);
    float mu = s * (1.0f / 128.0f);
    float qs = 0.f;
    float dv[8];
#pragma unroll
    for (int q = 0; q < 8; q++) { dv[q] = v[q] - mu; qs += dv[q] * dv[q]; }
#pragma unroll
    for (int o = 1; o < 16; o <<= 1) qs += __shfl_xor_sync(0xFFFFFFFFu, qs, o);
    float rstd = rsqrtf(qs * (1.0f / 128.0f) + 1e-5f);

    float4 g0 = *(const float4*)(lg + hl * 8);
    float4 g1 = *(const float4*)(lg + hl * 8 + 4);
    float4 p0 = *(const float4*)(lb + hl * 8);
    float4 p1 = *(const float4*)(lb + hl * 8 + 4);
    float ov[8];
    ov[0] = dv[0] * rstd * g0.x + p0.x; ov[1] = dv[1] * rstd * g0.y + p0.y;
    ov[2] = dv[2] * rstd * g0.z + p0.z; ov[3] = dv[3] * rstd * g0.w + p0.w;
    ov[4] = dv[4] * rstd * g1.x + p1.x; ov[5] = dv[5] * rstd * g1.y + p1.y;
    ov[6] = dv[6] * rstd * g1.z + p1.z; ov[7] = dv[7] * rstd * g1.w + p1.w;

    if (half == 0) {
        if (layer == 0) {
            __half2 h0 = __floats2half2_rn(ov[0], ov[1]);
            __half2 h1 = __floats2half2_rn(ov[2], ov[3]);
            __half2 h2 = __floats2half2_rn(ov[4], ov[5]);
            __half2 h3 = __floats2half2_rn(ov[6], ov[7]);
            float2 f0 = __half22float2(h0), f1 = __half22float2(h1);
            float2 f2 = __half22float2(h2), f3 = __half22float2(h3);
            __half2 l0 = __floats2half2_rn(ov[0] - f0.x, ov[1] - f0.y);
            __half2 l1 = __floats2half2_rn(ov[2] - f1.x, ov[3] - f1.y);
            __half2 l2 = __floats2half2_rn(ov[4] - f2.x, ov[5] - f2.y);
            __half2 l3 = __floats2half2_rn(ov[6] - f3.x, ov[7] - f3.y);
            *(uint4*)(g_Ah + (size_t)n * 128 + hl * 8) =
                make_uint4(h2_as_u32(h0), h2_as_u32(h1), h2_as_u32(h2), h2_as_u32(h3));
            *(uint4*)(g_Al + (size_t)n * 128 + hl * 8) =
                make_uint4(h2_as_u32(l0), h2_as_u32(l1), h2_as_u32(l2), h2_as_u32(l3));
        } else {
            *(float4*)(enc_out + (size_t)n * 128 + hl * 8) =
                make_float4(ov[0], ov[1], ov[2], ov[3]);
            *(float4*)(enc_out + (size_t)n * 128 + hl * 8 + 4) =
                make_float4(ov[4], ov[5], ov[6], ov[7]);
        }
    }
}

__global__ void k_wt(const float* __restrict__ Wih_f, const float* __restrict__ Whh_f,
                     const float* __restrict__ Wih_b, const float* __restrict__ Whh_b) {
    int idx = blockIdx.x * blockDim.x + threadIdx.x;
    if (idx >= 2 * 384 * 512) return;
    int dir = idx / (384 * 512);
    int rem = idx % (384 * 512);
    int d = rem / 512, j = rem % 512;
    const float* Wih = dir ? Wih_b : Wih_f;
    const float* Whh = dir ? Whh_b : Whh_f;
    float v = (d < 256) ? Wih[j * 256 + d] : Whh[j * 128 + (d - 256)];
    g_WT[dir][rem] = v;
}

// ---------------- LSTM input projection (seq build fused in) ----------------
__global__ __launch_bounds__(512) void k_xgate(const float* __restrict__ enc,
                                               const int* __restrict__ pn,
                                               const int* __restrict__ pr,
                                               const float* __restrict__ rel,
                                               const float* __restrict__ bf,
                                               const float* __restrict__ bb) {
    __shared__ float xt[256];
    int pl = blockIdx.x;               // p*4 + t
    int p = pl >> 2, tt = pl & 3;
    int dir = blockIdx.y;
    int j = threadIdx.x;
    const float* WT = g_WT[dir];
    const float* bias = dir ? bb : bf;
    if (j < 128) {
        int node = pn[p * 4 + tt];
        xt[j] = enc[(size_t)node * 128 + j];
    } else if (j < 256) {
        int d = j - 128;
        float rv = 0.0f;
        if (tt > 0) { int r = pr[p * 3 + (tt - 1)]; rv = rel[r * 128 + d]; }
        xt[j] = rv;
    }
    __syncthreads();
    float acc = bias[j];
    for (int d = 0; d < 256; d++) acc = fmaf(WT[d * 512 + j], xt[d], acc);
    g_gx[((size_t)dir * 1024 + pl) * 512 + j] = acc;
}

// ---------------- bidirectional LSTM: recurrent part only (K=128) ----------------
__global__ __launch_bounds__(512) void k_lstm() {
    const int PB = 8;
    __shared__ float hs[PB][128];
    __shared__ float cs[PB][128];
    __shared__ float gs[PB][512];
    int dir = blockIdx.y;
    const float* WT = g_WT[dir];
    int p0 = blockIdx.x * PB;
    int t = threadIdx.x;

    for (int i = t; i < PB * 128; i += 512) { ((float*)hs)[i] = 0.0f; ((float*)cs)[i] = 0.0f; }
    __syncthreads();

    for (int step = 0; step < 4; step++) {
        int tt = dir ? (3 - step) : step;
        float acc[PB];
#pragma unroll
        for (int p = 0; p < PB; p++)
            acc[p] = g_gx[((size_t)dir * 1024 + (p0 + p) * 4 + tt) * 512 + t];
        for (int d = 0; d < 128; d++) {
            float w = WT[(256 + d) * 512 + t];
#pragma unroll
            for (int p = 0; p < PB; p++) acc[p] = fmaf(w, hs[p][d], acc[p]);
        }
#pragma unroll
        for (int p = 0; p < PB; p++) gs[p][t] = acc[p];
        __syncthreads();
        for (int i = t; i < PB * 128; i += 512) {
            int pp = i >> 7, k = i & 127;
            float ig = 1.0f / (1.0f + expf(-gs[pp][k]));
            float fg = 1.0f / (1.0f + expf(-gs[pp][128 + k]));
            float gg = tanhf(gs[pp][256 + k]);
            float og = 1.0f / (1.0f + expf(-gs[pp][384 + k]));
            float c = fg * cs[pp][k] + ig * gg;
            cs[pp][k] = c;
            hs[pp][k] = og * tanhf(c);
        }
        __syncthreads();
    }
    for (int i = t; i < PB * 128; i += 512) {
        int pp = i >> 7, k = i & 127;
        g_h[((size_t)dir * 256 + p0 + pp) * 128 + k] = hs[pp][k];
    }
}

// ---------------- output head ----------------
__global__ void k_head(const float* __restrict__ Wop, const float* __restrict__ bop,
                       const float* __restrict__ q, const float* __restrict__ Ws1,
                       const float* __restrict__ bs1, const float* __restrict__ Ws2,
                       const float* __restrict__ bs2,
                       float* __restrict__ pe_out, float* __restrict__ sim_out) {
    int p = blockIdx.x;
    int k = threadIdx.x;
    __shared__ float cat[256];
    __shared__ float cat2[256];
    __shared__ float red[4];
    cat[k]       = g_h[(size_t)p * 128 + k];
    cat[128 + k] = g_h[(size_t)(256 + p) * 128 + k];
    __syncthreads();
    float acc = bop[k];
    for (int j = 0; j < 256; j++) acc = fmaf(cat[j], Wop[k * 256 + j], acc);
    float pe = fmaxf(acc, 0.0f);
    pe_out[(size_t)p * 128 + k] = pe;
    cat2[k] = pe;
    cat2[128 + k] = q[k];
    __syncthreads();
    float a2 = bs1[k];
    for (int j = 0; j < 256; j++) a2 = fmaf(cat2[j], Ws1[k * 256 + j], a2);
    float hdn = fmaxf(a2, 0.0f);
    float s = hdn * Ws2[k];
#pragma unroll
    for (int o = 16; o > 0; o >>= 1) s += __shfl_xor_sync(0xFFFFFFFFu, s, o);
    if ((k & 31) == 0) red[k >> 5] = s;
    __syncthreads();
    if (k == 0) {
        float tot = red[0] + red[1] + red[2] + red[3] + bs2[0];
        sim_out[p] = 1.0f / (1.0f + expf(-tot));
    }
}

// ---------------- launch ----------------
extern "C" void kernel_launch(void* const* d_in, const int* in_sizes, int n_in,
                              void* d_out, int out_size) {
    const float* node_features = (const float*)d_in[0];
    const int*   edge_index    = (const int*)d_in[1];
    const int*   edge_types    = (const int*)d_in[2];
    const float* query         = (const float*)d_in[3];
    const int*   path_nodes    = (const int*)d_in[4];
    const int*   path_rel      = (const int*)d_in[5];
    const float* W_self        = (const float*)d_in[6];
    const float* b_self        = (const float*)d_in[7];
    const float* W_rel         = (const float*)d_in[8];
    const float* ln_g          = (const float*)d_in[9];
    const float* ln_b          = (const float*)d_in[10];
    const float* rel_emb       = (const float*)d_in[11];
    const float* W_ih_f        = (const float*)d_in[12];
    const float* W_hh_f        = (const float*)d_in[13];
    const float* b_f           = (const float*)d_in[14];
    const float* W_ih_b        = (const float*)d_in[15];
    const float* W_hh_b        = (const float*)d_in[16];
    const float* b_b           = (const float*)d_in[17];
    const float* W_op          = (const float*)d_in[18];
    const float* b_op          = (const float*)d_in[19];
    const float* W_s1          = (const float*)d_in[20];
    const float* b_s1          = (const float*)d_in[21];
    const float* W_s2          = (const float*)d_in[22];
    const float* b_s2          = (const float*)d_in[23];
    (void)n_in; (void)out_size;

    const int N = in_sizes[0] / 128;
    const int E = in_sizes[1] / 2;
    const int P = in_sizes[4] / 4;

    float* out     = (float*)d_out;
    float* enc_out = out;
    float* pe_out  = out + (size_t)N * 128;
    float* sim_out = pe_out + (size_t)P * 128;

    const int* src = edge_index;
    const int* dst = edge_index + E;

    cudaFuncSetAttribute(k_gemm, cudaFuncAttributeMaxDynamicSharedMemorySize, GSMEM);

    // order chosen so k_gemm is the 4th launch (ncu capture slot)
    k_conv<<<(MPAD * 32 + 255) / 256, 256>>>(node_features, N);
    k_packb<<<(2 * NCOL * 128 + 255) / 256, 256>>>(W_rel, W_self);
    k_wt<<<(2 * 384 * 512 + 255) / 256, 256>>>(W_ih_f, W_hh_f, W_ih_b, W_hh_b);
    k_gemm<<<MPAD / 128, 256, GSMEM>>>(0);

    k_zero_cnt<<<(N + 255) / 256, 256>>>(N);
    k_hist<<<(E + 255) / 256, 256>>>(dst, E);
    k_scan<<<1, 1024>>>(N);
    k_place<<<(E + 255) / 256, 256>>>(src, dst, edge_types, E);

    k_gather<<<(N + 7) / 8, 256>>>(b_self, ln_g, ln_b, enc_out, 0, N);
    k_gemm<<<MPAD / 128, 256, GSMEM>>>(1);
    k_gather<<<(N + 7) / 8, 256>>>(b_self + 128, ln_g + 128, ln_b + 128, enc_out, 1, N);

    k_xgate<<<dim3(P * 4, 2), 512>>>(enc_out, path_nodes, path_rel, rel_emb, b_f, b_b);
    k_lstm<<<dim3(P / 8, 2), 512>>>();
    k_head<<<P, 128>>>(W_op, b_op, query, W_s1, b_s1, W_s2, b_s2, pe_out, sim_out);
}

// round 13
// speedup vs baseline: 1.7145x; 1.0549x over previous
#include <cuda_runtime.h>
#include <cuda_fp16.h>
#include <math.h>
#include <stdint.h>

#define D 128
#define R 16
#define NCOL 2176
#define MPAD 50048         // 391 * 128
#define NMAX 50000
#define EMAX 800000

// ---------------- scratch (device globals; allocation-free) ----------------
__device__ __half g_trans16[(size_t)MPAD * 2048];  // 204 MB, relation messages
__device__ float g_self[(size_t)MPAD * 128];
__device__ __half g_Ah[(size_t)MPAD * 128];
__device__ __half g_Al[(size_t)MPAD * 128];
__device__ __half g_Bh2[2][NCOL * 128];             // both layers packed upfront
__device__ float g_WT[2][384 * 512];
__device__ float g_gx[2 * 256 * 4 * 512];           // precomputed x-gates [dir][p*4+t][512]
__device__ float g_h[2 * 256 * 128];
// CSR
__device__ int g_cnt[NMAX];
__device__ int g_off[NMAX + 1];
__device__ int g_cur[NMAX];
__device__ uint32_t g_sed[EMAX];   // packed src | (r<<16)

// ---------------- bit-cast helpers ----------------
__device__ __forceinline__ uint32_t h2_as_u32(__half2 h) {
    uint32_t u; *(__half2*)&u = h; return u;
}
__device__ __forceinline__ __half2 u32_as_h2(uint32_t u) {
    __half2 h; *(uint32_t*)&h = u; return h;
}

// ---------------- PTX helpers ----------------
__device__ __forceinline__ uint32_t smem_u32(const void* p) {
    return (uint32_t)__cvta_generic_to_shared(p);
}
__device__ __forceinline__ void ldm_x4(uint32_t& r0, uint32_t& r1, uint32_t& r2, uint32_t& r3,
                                       uint32_t a) {
    asm volatile("ldmatrix.sync.aligned.m8n8.x4.shared.b16 {%0,%1,%2,%3}, [%4];"
                 : "=r"(r0), "=r"(r1), "=r"(r2), "=r"(r3) : "r"(a));
}
__device__ __forceinline__ void ldm_x2(uint32_t& r0, uint32_t& r1, uint32_t a) {
    asm volatile("ldmatrix.sync.aligned.m8n8.x2.shared.b16 {%0,%1}, [%2];"
                 : "=r"(r0), "=r"(r1) : "r"(a));
}
__device__ __forceinline__ void mma16816(float* c, uint32_t a0, uint32_t a1, uint32_t a2,
                                         uint32_t a3, uint32_t b0, uint32_t b1) {
    asm volatile(
        "mma.sync.aligned.m16n8k16.row.col.f32.f16.f16.f32 "
        "{%0,%1,%2,%3}, {%4,%5,%6,%7}, {%8,%9}, {%0,%1,%2,%3};"
        : "+f"(c[0]), "+f"(c[1]), "+f"(c[2]), "+f"(c[3])
        : "r"(a0), "r"(a1), "r"(a2), "r"(a3), "r"(b0), "r"(b1));
}
__device__ __forceinline__ void cpa16(uint32_t dst, const void* src) {
    asm volatile("cp.async.cg.shared.global [%0], [%1], 16;" :: "r"(dst), "l"(src));
}

// ---------------- CSR build ----------------
__global__ void k_zero_cnt(int N) {
    int i = blockIdx.x * blockDim.x + threadIdx.x;
    if (i < N) g_cnt[i] = 0;
}
__global__ void k_hist(const int* __restrict__ dst, int E) {
    int e = blockIdx.x * blockDim.x + threadIdx.x;
    if (e < E) atomicAdd(&g_cnt[dst[e]], 1);
}
__global__ __launch_bounds__(1024) void k_scan(int N) {
    __shared__ int sh[1024];
    int t = threadIdx.x;
    int chunk = (N + 1023) / 1024;
    int c0 = t * chunk, c1 = min(c0 + chunk, N);
    int s = 0;
    for (int i = c0; i < c1; i++) s += g_cnt[i];
    sh[t] = s;
    __syncthreads();
    for (int o = 1; o < 1024; o <<= 1) {
        int v = (t >= o) ? sh[t - o] : 0;
        __syncthreads();
        sh[t] += v;
        __syncthreads();
    }
    int run = sh[t] - s;
    for (int i = c0; i < c1; i++) {
        g_off[i] = run;
        g_cur[i] = run;
        run += g_cnt[i];
    }
    if (t == 1023) g_off[N] = run;
}
__global__ void k_place(const int* __restrict__ src, const int* __restrict__ dst,
                        const int* __restrict__ et, int E) {
    int e = blockIdx.x * blockDim.x + threadIdx.x;
    if (e >= E) return;
    int pos = atomicAdd(&g_cur[dst[e]], 1);
    g_sed[pos] = (uint32_t)src[e] | ((uint32_t)et[e] << 16);
}

// ---------------- conversions ----------------
__global__ void k_conv(const float* __restrict__ x0, int Nn) {
    int i4 = blockIdx.x * blockDim.x + threadIdx.x;
    if (i4 >= MPAD * 32) return;
    int row = i4 >> 5;
    float4 v = make_float4(0.f, 0.f, 0.f, 0.f);
    if (row < Nn) v = *(const float4*)(x0 + (size_t)i4 * 4);
    __half2 h0 = __floats2half2_rn(v.x, v.y);
    __half2 h1 = __floats2half2_rn(v.z, v.w);
    float2 f0 = __half22float2(h0), f1 = __half22float2(h1);
    __half2 l0 = __floats2half2_rn(v.x - f0.x, v.y - f0.y);
    __half2 l1 = __floats2half2_rn(v.z - f1.x, v.w - f1.y);
    ((uint2*)g_Ah)[i4] = make_uint2(h2_as_u32(h0), h2_as_u32(h1));
    ((uint2*)g_Al)[i4] = make_uint2(h2_as_u32(l0), h2_as_u32(l1));
}

__global__ void k_packb(const float* __restrict__ Wrel, const float* __restrict__ Wself) {
    int idx0 = blockIdx.x * blockDim.x + threadIdx.x;
    if (idx0 >= 2 * NCOL * 128) return;
    int l = idx0 / (NCOL * 128);
    int idx = idx0 % (NCOL * 128);
    int n = idx >> 7, d = idx & 127;
    const float* Wr = Wrel + (size_t)l * R * 128 * 128;
    const float* Ws = Wself + (size_t)l * 128 * 128;
    float v;
    if (n < 2048) {
        int r = n >> 7, k = n & 127;
        v = Wr[((size_t)r * 128 + d) * 128 + k];
    } else {
        v = Ws[d * 128 + (n - 2048)];
    }
    g_Bh2[l][idx] = __float2half_rn(v);
}

// ---------------- shared GEMM helpers ----------------
__device__ __forceinline__ void load_tile(char* dstbase, const __half* g, int row0, int t) {
#pragma unroll
    for (int it = 0; it < 8; it++) {
        int cl = it * 256 + t;
        int row = cl >> 4, c = cl & 15;
        uint4 v = *(const uint4*)(g + (size_t)(row0 + row) * 128 + c * 8);
        *(uint4*)(dstbase + row * 256 + ((c ^ (row & 7)) * 16)) = v;
    }
}

__device__ __forceinline__ void prefetch_b(uint32_t dstb, const __half* gsrc, int t) {
#pragma unroll
    for (int it = 0; it < 8; it++) {
        int cl = it * 256 + t;
        int row = cl >> 4, c = cl & 15;
        cpa16(dstb + row * 256 + ((c ^ (row & 7)) * 16), gsrc + (size_t)row * 128 + c * 8);
    }
    asm volatile("cp.async.commit_group;");
}

// ---------------- message GEMM: 16 n-tiles, single pass, 2 CTAs/SM ----------------
#define MM_AH 0
#define MM_B0 32768
#define MM_B1 65536
#define MSMEM 98304

__global__ __launch_bounds__(256, 2) void k_gemmM(int layer) {
    extern __shared__ char smem[];
    int t = threadIdx.x, lane = t & 31, w = t >> 5;
    int m0 = blockIdx.x * 128;
    uint32_t sbase = smem_u32(smem);
    const __half* Bh = g_Bh2[layer];

    prefetch_b(sbase + MM_B0, Bh, t);
    load_tile(smem + MM_AH, g_Ah, m0, t);

    int wm = (w & 1) * 64, wn = (w >> 1) * 32;
    int atile = lane >> 3, ar = lane & 7;
    int arow_base = wm + ((atile & 1) << 3) + ar;
    int achunk_sel = atile >> 1;
    int bl = lane & 15;
    int bhalf = bl >> 3, br = bl & 7;

    for (int n = 0; n < 16; n++) {
        uint32_t boff = (n & 1) ? MM_B1 : MM_B0;
        uint32_t bbase = sbase + boff;
        asm volatile("cp.async.wait_group 0;");
        __syncthreads();
        if (n + 1 < 16) {
            prefetch_b(sbase + (((n + 1) & 1) ? MM_B1 : MM_B0),
                       Bh + (size_t)(n + 1) * 128 * 128, t);
        }

        float acc[4][4][4];
#pragma unroll
        for (int i = 0; i < 4; i++)
#pragma unroll
            for (int j = 0; j < 4; j++)
#pragma unroll
                for (int q = 0; q < 4; q++) acc[i][j][q] = 0.0f;

#pragma unroll
        for (int ks = 0; ks < 8; ks++) {
            uint32_t a[4][4];
            uint32_t b[4][2];
            int ac = ks * 2 + achunk_sel;
#pragma unroll
            for (int i = 0; i < 4; i++) {
                int row = arow_base + i * 16;
                ldm_x4(a[i][0], a[i][1], a[i][2], a[i][3],
                       sbase + MM_AH + row * 256 + ((ac ^ (row & 7)) * 16));
            }
            int bc = ks * 2 + bhalf;
#pragma unroll
            for (int j = 0; j < 4; j++) {
                int row = wn + j * 8 + br;
                ldm_x2(b[j][0], b[j][1], bbase + row * 256 + ((bc ^ (row & 7)) * 16));
            }
#pragma unroll
            for (int i = 0; i < 4; i++)
#pragma unroll
                for (int j = 0; j < 4; j++)
                    mma16816(acc[i][j], a[i][0], a[i][1], a[i][2], a[i][3], b[j][0], b[j][1]);
        }
        __syncthreads();   // all warps done reading B buffer; reuse as fp16 C staging

        // stage fp16 C in the consumed B buffer: row stride 256B, 16B-block XOR swizzle
        char* cs = smem + boff;
#pragma unroll
        for (int i = 0; i < 4; i++) {
#pragma unroll
            for (int j = 0; j < 4; j++) {
                int r = wm + i * 16 + (lane >> 2);
                int cb = (wn + j * 8 + 2 * (lane & 3)) * 2;
                uint32_t off0 = r * 256 + ((((cb >> 4) ^ (r & 7)) << 4) | (cb & 15));
                uint32_t off1 = (r + 8) * 256 + ((((cb >> 4) ^ ((r + 8) & 7)) << 4) | (cb & 15));
                *(__half2*)(cs + off0) = __floats2half2_rn(acc[i][j][0], acc[i][j][1]);
                *(__half2*)(cs + off1) = __floats2half2_rn(acc[i][j][2], acc[i][j][3]);
            }
        }
        __syncthreads();
#pragma unroll
        for (int it = 0; it < 8; it++) {
            int idx = it * 256 + t;            // 2048 chunks: 128 rows x 16 x 16B
            int row = idx >> 4, ch = idx & 15;
            uint4 v = *(const uint4*)(cs + row * 256 + ((ch ^ (row & 7)) << 4));
            *(uint4*)(g_trans16 + (size_t)(m0 + row) * 2048 + n * 128 + ch * 8) = v;
        }
        __syncthreads();   // readout done before this buffer is prefetched again
    }
}

// ---------------- self GEMM: 2-pass split precision, fp32 out ----------------
#define SS_AH 0
#define SS_AL 32768
#define SS_BW 65536
#define SS_C  98304
#define SSMEM (98304 + 69632)

__global__ __launch_bounds__(256, 1) void k_gemmS(int layer) {
    extern __shared__ char smem[];
    int t = threadIdx.x, lane = t & 31, w = t >> 5;
    int m0 = blockIdx.x * 128;
    uint32_t sbase = smem_u32(smem);

    load_tile(smem + SS_AH, g_Ah, m0, t);
    load_tile(smem + SS_AL, g_Al, m0, t);
    load_tile(smem + SS_BW, g_Bh2[layer] + (size_t)2048 * 128, 0, t);
    __syncthreads();

    int wm = (w & 1) * 64, wn = (w >> 1) * 32;
    int atile = lane >> 3, ar = lane & 7;
    int arow_base = wm + ((atile & 1) << 3) + ar;
    int achunk_sel = atile >> 1;
    int bl = lane & 15;
    int bhalf = bl >> 3, br = bl & 7;

    float acc[4][4][4];
#pragma unroll
    for (int i = 0; i < 4; i++)
#pragma unroll
        for (int j = 0; j < 4; j++)
#pragma unroll
            for (int q = 0; q < 4; q++) acc[i][j][q] = 0.0f;

#pragma unroll
    for (int pass = 0; pass < 2; pass++) {
        uint32_t abase = sbase + (pass ? SS_AL : SS_AH);
#pragma unroll
        for (int ks = 0; ks < 8; ks++) {
            uint32_t a[4][4];
            uint32_t b[4][2];
            int ac = ks * 2 + achunk_sel;
#pragma unroll
            for (int i = 0; i < 4; i++) {
                int row = arow_base + i * 16;
                ldm_x4(a[i][0], a[i][1], a[i][2], a[i][3],
                       abase + row * 256 + ((ac ^ (row & 7)) * 16));
            }
            int bc = ks * 2 + bhalf;
#pragma unroll
            for (int j = 0; j < 4; j++) {
                int row = wn + j * 8 + br;
                ldm_x2(b[j][0], b[j][1], sbase + SS_BW + row * 256 + ((bc ^ (row & 7)) * 16));
            }
#pragma unroll
            for (int i = 0; i < 4; i++)
#pragma unroll
                for (int j = 0; j < 4; j++)
                    mma16816(acc[i][j], a[i][0], a[i][1], a[i][2], a[i][3], b[j][0], b[j][1]);
        }
    }
    __syncthreads();

    float* cs = (float*)(smem + SS_C);
#pragma unroll
    for (int i = 0; i < 4; i++) {
#pragma unroll
        for (int j = 0; j < 4; j++) {
            int r = wm + i * 16 + (lane >> 2);
            int c = wn + j * 8 + 2 * (lane & 3);
            *(float2*)(cs + r * 136 + c) = make_float2(acc[i][j][0], acc[i][j][1]);
            *(float2*)(cs + (r + 8) * 136 + c) = make_float2(acc[i][j][2], acc[i][j][3]);
        }
    }
    __syncthreads();
#pragma unroll
    for (int it = 0; it < 16; it++) {
        int idx = it * 256 + t;
        int row = idx >> 5, c4 = (idx & 31) * 4;
        float4 v = *(const float4*)(cs + row * 136 + c4);
        *(float4*)(g_self + (size_t)(m0 + row) * 128 + c4) = v;
    }
}

// ---------------- fused gather + update: warp per node, half-warp per edge ----------------
__device__ __forceinline__ void acc8(float* a, uint4 r) {
    float2 f;
    f = __half22float2(u32_as_h2(r.x)); a[0] += f.x; a[1] += f.y;
    f = __half22float2(u32_as_h2(r.y)); a[2] += f.x; a[3] += f.y;
    f = __half22float2(u32_as_h2(r.z)); a[4] += f.x; a[5] += f.y;
    f = __half22float2(u32_as_h2(r.w)); a[6] += f.x; a[7] += f.y;
}
__device__ __forceinline__ uint4 ldg_msg(const __half* p) {
    return __ldg((const uint4*)p);
}

__global__ __launch_bounds__(256) void k_gather(const float* __restrict__ bself,
                                                const float* __restrict__ lg,
                                                const float* __restrict__ lb,
                                                float* __restrict__ enc_out,
                                                int layer, int M) {
    int n = blockIdx.x * 8 + (threadIdx.x >> 5);
    int lane = threadIdx.x & 31;
    if (n >= M) return;
    int half = lane >> 4, hl = lane & 15;
    int beg = g_off[n], end = g_off[n + 1];

    float acc[8];
#pragma unroll
    for (int q = 0; q < 8; q++) acc[q] = 0.0f;

    int e = beg + half;
    for (; e + 6 < end; e += 8) {
        uint32_t p0 = g_sed[e], p1 = g_sed[e + 2], p2 = g_sed[e + 4], p3 = g_sed[e + 6];
        uint4 r0 = ldg_msg(g_trans16 + (size_t)(p0 & 0xFFFF) * 2048 + ((p0 >> 16) << 7) + hl * 8);
        uint4 r1 = ldg_msg(g_trans16 + (size_t)(p1 & 0xFFFF) * 2048 + ((p1 >> 16) << 7) + hl * 8);
        uint4 r2 = ldg_msg(g_trans16 + (size_t)(p2 & 0xFFFF) * 2048 + ((p2 >> 16) << 7) + hl * 8);
        uint4 r3 = ldg_msg(g_trans16 + (size_t)(p3 & 0xFFFF) * 2048 + ((p3 >> 16) << 7) + hl * 8);
        acc8(acc, r0); acc8(acc, r1); acc8(acc, r2); acc8(acc, r3);
    }
    for (; e < end; e += 2) {
        uint32_t p = g_sed[e];
        uint4 r = ldg_msg(g_trans16 + (size_t)(p & 0xFFFF) * 2048 + ((p >> 16) << 7) + hl * 8);
        acc8(acc, r);
    }
#pragma unroll
    for (int q = 0; q < 8; q++) acc[q] += __shfl_xor_sync(0xFFFFFFFFu, acc[q], 16);

    float inv = 1.0f / fmaxf((float)(end - beg), 1.0f);
    float4 s0 = *(const float4*)(g_self + (size_t)n * 128 + hl * 8);
    float4 s1 = *(const float4*)(g_self + (size_t)n * 128 + hl * 8 + 4);
    float4 b0 = *(const float4*)(bself + hl * 8);
    float4 b1 = *(const float4*)(bself + hl * 8 + 4);
    float v[8];
    v[0] = fmaxf(s0.x + b0.x + acc[0] * inv, 0.f);
    v[1] = fmaxf(s0.y + b0.y + acc[1] * inv, 0.f);
    v[2] = fmaxf(s0.z + b0.z + acc[2] * inv, 0.f);
    v[3] = fmaxf(s0.w + b0.w + acc[3] * inv, 0.f);
    v[4] = fmaxf(s1.x + b1.x + acc[4] * inv, 0.f);
    v[5] = fmaxf(s1.y + b1.y + acc[5] * inv, 0.f);
    v[6] = fmaxf(s1.z + b1.z + acc[6] * inv, 0.f);
    v[7] = fmaxf(s1.w + b1.w + acc[7] * inv, 0.f);

    float s = 0.f;
#pragma unroll
    for (int q = 0; q < 8; q++) s += v[q];
#pragma unroll
    for (int o = 1; o < 16; o <<= 1) s += __shfl_xor_sync(0xFFFFFFFFu, s, o);
    float mu = s * (1.0f / 128.0f);
    float qs = 0.f;
    float dv[8];
#pragma unroll
    for (int q = 0; q < 8; q++) { dv[q] = v[q] - mu; qs += dv[q] * dv[q]; }
#pragma unroll
    for (int o = 1; o < 16; o <<= 1) qs += __shfl_xor_sync(0xFFFFFFFFu, qs, o);
    float rstd = rsqrtf(qs * (1.0f / 128.0f) + 1e-5f);

    float4 g0 = *(const float4*)(lg + hl * 8);
    float4 g1 = *(const float4*)(lg + hl * 8 + 4);
    float4 p0 = *(const float4*)(lb + hl * 8);
    float4 p1 = *(const float4*)(lb + hl * 8 + 4);
    float ov[8];
    ov[0] = dv[0] * rstd * g0.x + p0.x; ov[1] = dv[1] * rstd * g0.y + p0.y;
    ov[2] = dv[2] * rstd * g0.z + p0.z; ov[3] = dv[3] * rstd * g0.w + p0.w;
    ov[4] = dv[4] * rstd * g1.x + p1.x; ov[5] = dv[5] * rstd * g1.y + p1.y;
    ov[6] = dv[6] * rstd * g1.z + p1.z; ov[7] = dv[7] * rstd * g1.w + p1.w;

    if (half == 0) {
        if (layer == 0) {
            __half2 h0 = __floats2half2_rn(ov[0], ov[1]);
            __half2 h1 = __floats2half2_rn(ov[2], ov[3]);
            __half2 h2 = __floats2half2_rn(ov[4], ov[5]);
            __half2 h3 = __floats2half2_rn(ov[6], ov[7]);
            float2 f0 = __half22float2(h0), f1 = __half22float2(h1);
            float2 f2 = __half22float2(h2), f3 = __half22float2(h3);
            __half2 l0 = __floats2half2_rn(ov[0] - f0.x, ov[1] - f0.y);
            __half2 l1 = __floats2half2_rn(ov[2] - f1.x, ov[3] - f1.y);
            __half2 l2 = __floats2half2_rn(ov[4] - f2.x, ov[5] - f2.y);
            __half2 l3 = __floats2half2_rn(ov[6] - f3.x, ov[7] - f3.y);
            *(uint4*)(g_Ah + (size_t)n * 128 + hl * 8) =
                make_uint4(h2_as_u32(h0), h2_as_u32(h1), h2_as_u32(h2), h2_as_u32(h3));
            *(uint4*)(g_Al + (size_t)n * 128 + hl * 8) =
                make_uint4(h2_as_u32(l0), h2_as_u32(l1), h2_as_u32(l2), h2_as_u32(l3));
        } else {
            *(float4*)(enc_out + (size_t)n * 128 + hl * 8) =
                make_float4(ov[0], ov[1], ov[2], ov[3]);
            *(float4*)(enc_out + (size_t)n * 128 + hl * 8 + 4) =
                make_float4(ov[4], ov[5], ov[6], ov[7]);
        }
    }
}

__global__ void k_wt(const float* __restrict__ Wih_f, const float* __restrict__ Whh_f,
                     const float* __restrict__ Wih_b, const float* __restrict__ Whh_b) {
    int idx = blockIdx.x * blockDim.x + threadIdx.x;
    if (idx >= 2 * 384 * 512) return;
    int dir = idx / (384 * 512);
    int rem = idx % (384 * 512);
    int d = rem / 512, j = rem % 512;
    const float* Wih = dir ? Wih_b : Wih_f;
    const float* Whh = dir ? Whh_b : Whh_f;
    float v = (d < 256) ? Wih[j * 256 + d] : Whh[j * 128 + (d - 256)];
    g_WT[dir][rem] = v;
}

// ---------------- LSTM input projection (seq build fused in) ----------------
__global__ __launch_bounds__(512) void k_xgate(const float* __restrict__ enc,
                                               const int* __restrict__ pn,
                                               const int* __restrict__ pr,
                                               const float* __restrict__ rel,
                                               const float* __restrict__ bf,
                                               const float* __restrict__ bb) {
    __shared__ float xt[256];
    int pl = blockIdx.x;               // p*4 + t
    int p = pl >> 2, tt = pl & 3;
    int dir = blockIdx.y;
    int j = threadIdx.x;
    const float* WT = g_WT[dir];
    const float* bias = dir ? bb : bf;
    if (j < 128) {
        int node = pn[p * 4 + tt];
        xt[j] = enc[(size_t)node * 128 + j];
    } else if (j < 256) {
        int d = j - 128;
        float rv = 0.0f;
        if (tt > 0) { int r = pr[p * 3 + (tt - 1)]; rv = rel[r * 128 + d]; }
        xt[j] = rv;
    }
    __syncthreads();
    float acc = bias[j];
    for (int d = 0; d < 256; d++) acc = fmaf(WT[d * 512 + j], xt[d], acc);
    g_gx[((size_t)dir * 1024 + pl) * 512 + j] = acc;
}

// ---------------- bidirectional LSTM: recurrent part only (K=128) ----------------
__global__ __launch_bounds__(512) void k_lstm() {
    const int PB = 8;
    __shared__ float hs[PB][128];
    __shared__ float cs[PB][128];
    __shared__ float gs[PB][512];
    int dir = blockIdx.y;
    const float* WT = g_WT[dir];
    int p0 = blockIdx.x * PB;
    int t = threadIdx.x;

    for (int i = t; i < PB * 128; i += 512) { ((float*)hs)[i] = 0.0f; ((float*)cs)[i] = 0.0f; }
    __syncthreads();

    for (int step = 0; step < 4; step++) {
        int tt = dir ? (3 - step) : step;
        float acc[PB];
#pragma unroll
        for (int p = 0; p < PB; p++)
            acc[p] = g_gx[((size_t)dir * 1024 + (p0 + p) * 4 + tt) * 512 + t];
        for (int d = 0; d < 128; d++) {
            float w = WT[(256 + d) * 512 + t];
#pragma unroll
            for (int p = 0; p < PB; p++) acc[p] = fmaf(w, hs[p][d], acc[p]);
        }
#pragma unroll
        for (int p = 0; p < PB; p++) gs[p][t] = acc[p];
        __syncthreads();
        for (int i = t; i < PB * 128; i += 512) {
            int pp = i >> 7, k = i & 127;
            float ig = 1.0f / (1.0f + expf(-gs[pp][k]));
            float fg = 1.0f / (1.0f + expf(-gs[pp][128 + k]));
            float gg = tanhf(gs[pp][256 + k]);
            float og = 1.0f / (1.0f + expf(-gs[pp][384 + k]));
            float c = fg * cs[pp][k] + ig * gg;
            cs[pp][k] = c;
            hs[pp][k] = og * tanhf(c);
        }
        __syncthreads();
    }
    for (int i = t; i < PB * 128; i += 512) {
        int pp = i >> 7, k = i & 127;
        g_h[((size_t)dir * 256 + p0 + pp) * 128 + k] = hs[pp][k];
    }
}

// ---------------- output head ----------------
__global__ void k_head(const float* __restrict__ Wop, const float* __restrict__ bop,
                       const float* __restrict__ q, const float* __restrict__ Ws1,
                       const float* __restrict__ bs1, const float* __restrict__ Ws2,
                       const float* __restrict__ bs2,
                       float* __restrict__ pe_out, float* __restrict__ sim_out) {
    int p = blockIdx.x;
    int k = threadIdx.x;
    __shared__ float cat[256];
    __shared__ float cat2[256];
    __shared__ float red[4];
    cat[k]       = g_h[(size_t)p * 128 + k];
    cat[128 + k] = g_h[(size_t)(256 + p) * 128 + k];
    __syncthreads();
    float acc = bop[k];
    for (int j = 0; j < 256; j++) acc = fmaf(cat[j], Wop[k * 256 + j], acc);
    float pe = fmaxf(acc, 0.0f);
    pe_out[(size_t)p * 128 + k] = pe;
    cat2[k] = pe;
    cat2[128 + k] = q[k];
    __syncthreads();
    float a2 = bs1[k];
    for (int j = 0; j < 256; j++) a2 = fmaf(cat2[j], Ws1[k * 256 + j], a2);
    float hdn = fmaxf(a2, 0.0f);
    float s = hdn * Ws2[k];
#pragma unroll
    for (int o = 16; o > 0; o >>= 1) s += __shfl_xor_sync(0xFFFFFFFFu, s, o);
    if ((k & 31) == 0) red[k >> 5] = s;
    __syncthreads();
    if (k == 0) {
        float tot = red[0] + red[1] + red[2] + red[3] + bs2[0];
        sim_out[p] = 1.0f / (1.0f + expf(-tot));
    }
}

// ---------------- launch ----------------
extern "C" void kernel_launch(void* const* d_in, const int* in_sizes, int n_in,
                              void* d_out, int out_size) {
    const float* node_features = (const float*)d_in[0];
    const int*   edge_index    = (const int*)d_in[1];
    const int*   edge_types    = (const int*)d_in[2];
    const float* query         = (const float*)d_in[3];
    const int*   path_nodes    = (const int*)d_in[4];
    const int*   path_rel      = (const int*)d_in[5];
    const float* W_self        = (const float*)d_in[6];
    const float* b_self        = (const float*)d_in[7];
    const float* W_rel         = (const float*)d_in[8];
    const float* ln_g          = (const float*)d_in[9];
    const float* ln_b          = (const float*)d_in[10];
    const float* rel_emb       = (const float*)d_in[11];
    const float* W_ih_f        = (const float*)d_in[12];
    const float* W_hh_f        = (const float*)d_in[13];
    const float* b_f           = (const float*)d_in[14];
    const float* W_ih_b        = (const float*)d_in[15];
    const float* W_hh_b        = (const float*)d_in[16];
    const float* b_b           = (const float*)d_in[17];
    const float* W_op          = (const float*)d_in[18];
    const float* b_op          = (const float*)d_in[19];
    const float* W_s1          = (const float*)d_in[20];
    const float* b_s1          = (const float*)d_in[21];
    const float* W_s2          = (const float*)d_in[22];
    const float* b_s2          = (const float*)d_in[23];
    (void)n_in; (void)out_size;

    const int N = in_sizes[0] / 128;
    const int E = in_sizes[1] / 2;
    const int P = in_sizes[4] / 4;

    float* out     = (float*)d_out;
    float* enc_out = out;
    float* pe_out  = out + (size_t)N * 128;
    float* sim_out = pe_out + (size_t)P * 128;

    const int* src = edge_index;
    const int* dst = edge_index + E;

    cudaFuncSetAttribute(k_gemmM, cudaFuncAttributeMaxDynamicSharedMemorySize, MSMEM);
    cudaFuncSetAttribute(k_gemmS, cudaFuncAttributeMaxDynamicSharedMemorySize, SSMEM);

    // order chosen so k_gemmM is the 4th launch (ncu capture slot)
    k_conv<<<(MPAD * 32 + 255) / 256, 256>>>(node_features, N);
    k_packb<<<(2 * NCOL * 128 + 255) / 256, 256>>>(W_rel, W_self);
    k_wt<<<(2 * 384 * 512 + 255) / 256, 256>>>(W_ih_f, W_hh_f, W_ih_b, W_hh_b);
    k_gemmM<<<MPAD / 128, 256, MSMEM>>>(0);
    k_gemmS<<<MPAD / 128, 256, SSMEM>>>(0);

    k_zero_cnt<<<(N + 255) / 256, 256>>>(N);
    k_hist<<<(E + 255) / 256, 256>>>(dst, E);
    k_scan<<<1, 1024>>>(N);
    k_place<<<(E + 255) / 256, 256>>>(src, dst, edge_types, E);

    k_gather<<<(N + 7) / 8, 256>>>(b_self, ln_g, ln_b, enc_out, 0, N);
    k_gemmM<<<MPAD / 128, 256, MSMEM>>>(1);
    k_gemmS<<<MPAD / 128, 256, SSMEM>>>(1);
    k_gather<<<(N + 7) / 8, 256>>>(b_self + 128, ln_g + 128, ln_b + 128, enc_out, 1, N);

    k_xgate<<<dim3(P * 4, 2), 512>>>(enc_out, path_nodes, path_rel, rel_emb, b_f, b_b);
    k_lstm<<<dim3(P / 8, 2), 512>>>();
    k_head<<<P, 128>>>(W_op, b_op, query, W_s1, b_s1, W_s2, b_s2, pe_out, sim_out);
}

// round 14
// speedup vs baseline: 1.8106x; 1.0560x over previous
#include <cuda_runtime.h>
#include <cuda_fp16.h>
#include <math.h>
#include <stdint.h>

#define D 128
#define R 16
#define NCOL 2176
#define MPAD 50048         // 391 * 128
#define NMAX 50000
#define EMAX 800000

// ---------------- scratch (device globals; allocation-free) ----------------
__device__ __half g_trans16[(size_t)MPAD * 2048];  // 204 MB, relation messages
__device__ float g_self[(size_t)MPAD * 128];
__device__ __half g_Ah[(size_t)MPAD * 128];
__device__ __half g_Al[(size_t)MPAD * 128];
__device__ __half g_Bh2[2][NCOL * 128];             // both layers packed upfront
__device__ float g_WT[2][384 * 512];
__device__ float g_gx[2 * 256 * 4 * 512];           // precomputed x-gates [dir][p*4+t][512]
__device__ float g_h[2 * 256 * 128];
// CSR
__device__ int g_cnt[NMAX];
__device__ int g_off[NMAX + 1];
__device__ int g_cur[NMAX];
__device__ uint32_t g_sed[EMAX];   // packed src | (r<<16)

// ---------------- bit-cast helpers ----------------
__device__ __forceinline__ uint32_t h2_as_u32(__half2 h) {
    uint32_t u; *(__half2*)&u = h; return u;
}
__device__ __forceinline__ __half2 u32_as_h2(uint32_t u) {
    __half2 h; *(uint32_t*)&h = u; return h;
}

// ---------------- PTX helpers ----------------
__device__ __forceinline__ uint32_t smem_u32(const void* p) {
    return (uint32_t)__cvta_generic_to_shared(p);
}
__device__ __forceinline__ void ldm_x4(uint32_t& r0, uint32_t& r1, uint32_t& r2, uint32_t& r3,
                                       uint32_t a) {
    asm volatile("ldmatrix.sync.aligned.m8n8.x4.shared.b16 {%0,%1,%2,%3}, [%4];"
                 : "=r"(r0), "=r"(r1), "=r"(r2), "=r"(r3) : "r"(a));
}
__device__ __forceinline__ void ldm_x2(uint32_t& r0, uint32_t& r1, uint32_t a) {
    asm volatile("ldmatrix.sync.aligned.m8n8.x2.shared.b16 {%0,%1}, [%2];"
                 : "=r"(r0), "=r"(r1) : "r"(a));
}
__device__ __forceinline__ void mma16816(float* c, uint32_t a0, uint32_t a1, uint32_t a2,
                                         uint32_t a3, uint32_t b0, uint32_t b1) {
    asm volatile(
        "mma.sync.aligned.m16n8k16.row.col.f32.f16.f16.f32 "
        "{%0,%1,%2,%3}, {%4,%5,%6,%7}, {%8,%9}, {%0,%1,%2,%3};"
        : "+f"(c[0]), "+f"(c[1]), "+f"(c[2]), "+f"(c[3])
        : "r"(a0), "r"(a1), "r"(a2), "r"(a3), "r"(b0), "r"(b1));
}
__device__ __forceinline__ void cpa16(uint32_t dst, const void* src) {
    asm volatile("cp.async.cg.shared.global [%0], [%1], 16;" :: "r"(dst), "l"(src));
}

// ---------------- CSR build ----------------
__global__ void k_hist(const int* __restrict__ dst, int E) {
    int e = blockIdx.x * blockDim.x + threadIdx.x;
    if (e < E) atomicAdd(&g_cnt[dst[e]], 1);
}
__global__ __launch_bounds__(1024) void k_scan(int N) {
    __shared__ int sh[1024];
    int t = threadIdx.x;
    int chunk = (N + 1023) / 1024;
    int c0 = t * chunk, c1 = min(c0 + chunk, N);
    int s = 0;
    for (int i = c0; i < c1; i++) s += g_cnt[i];
    sh[t] = s;
    __syncthreads();
    for (int o = 1; o < 1024; o <<= 1) {
        int v = (t >= o) ? sh[t - o] : 0;
        __syncthreads();
        sh[t] += v;
        __syncthreads();
    }
    int run = sh[t] - s;
    for (int i = c0; i < c1; i++) {
        g_off[i] = run;
        g_cur[i] = run;
        run += g_cnt[i];
    }
    if (t == 1023) g_off[N] = run;
}
__global__ void k_place(const int* __restrict__ src, const int* __restrict__ dst,
                        const int* __restrict__ et, int E) {
    int e = blockIdx.x * blockDim.x + threadIdx.x;
    if (e >= E) return;
    int pos = atomicAdd(&g_cur[dst[e]], 1);
    g_sed[pos] = (uint32_t)src[e] | ((uint32_t)et[e] << 16);
}

// ---------------- conversions (also zeroes g_cnt) ----------------
__global__ void k_conv(const float* __restrict__ x0, int Nn) {
    int i4 = blockIdx.x * blockDim.x + threadIdx.x;
    if (i4 >= MPAD * 32) return;
    if (i4 < NMAX) g_cnt[i4] = 0;
    int row = i4 >> 5;
    float4 v = make_float4(0.f, 0.f, 0.f, 0.f);
    if (row < Nn) v = *(const float4*)(x0 + (size_t)i4 * 4);
    __half2 h0 = __floats2half2_rn(v.x, v.y);
    __half2 h1 = __floats2half2_rn(v.z, v.w);
    float2 f0 = __half22float2(h0), f1 = __half22float2(h1);
    __half2 l0 = __floats2half2_rn(v.x - f0.x, v.y - f0.y);
    __half2 l1 = __floats2half2_rn(v.z - f1.x, v.w - f1.y);
    ((uint2*)g_Ah)[i4] = make_uint2(h2_as_u32(h0), h2_as_u32(h1));
    ((uint2*)g_Al)[i4] = make_uint2(h2_as_u32(l0), h2_as_u32(l1));
}

__global__ void k_packb(const float* __restrict__ Wrel, const float* __restrict__ Wself) {
    int idx0 = blockIdx.x * blockDim.x + threadIdx.x;
    if (idx0 >= 2 * NCOL * 128) return;
    int l = idx0 / (NCOL * 128);
    int idx = idx0 % (NCOL * 128);
    int n = idx >> 7, d = idx & 127;
    const float* Wr = Wrel + (size_t)l * R * 128 * 128;
    const float* Ws = Wself + (size_t)l * 128 * 128;
    float v;
    if (n < 2048) {
        int r = n >> 7, k = n & 127;
        v = Wr[((size_t)r * 128 + d) * 128 + k];
    } else {
        v = Ws[d * 128 + (n - 2048)];
    }
    g_Bh2[l][idx] = __float2half_rn(v);
}

// ---------------- shared GEMM helpers ----------------
__device__ __forceinline__ void load_tile(char* dstbase, const __half* g, int row0, int t) {
#pragma unroll
    for (int it = 0; it < 8; it++) {
        int cl = it * 256 + t;
        int row = cl >> 4, c = cl & 15;
        uint4 v = *(const uint4*)(g + (size_t)(row0 + row) * 128 + c * 8);
        *(uint4*)(dstbase + row * 256 + ((c ^ (row & 7)) * 16)) = v;
    }
}

__device__ __forceinline__ void prefetch_b(uint32_t dstb, const __half* gsrc, int t) {
#pragma unroll
    for (int it = 0; it < 8; it++) {
        int cl = it * 256 + t;
        int row = cl >> 4, c = cl & 15;
        cpa16(dstb + row * 256 + ((c ^ (row & 7)) * 16), gsrc + (size_t)row * 128 + c * 8);
    }
    asm volatile("cp.async.commit_group;");
}

// ---------------- unified GEMM: 17 n-tiles, single pass, 2 CTAs/SM ----------------
// Tiles 0..15: fp16 messages (C staged in consumed B buffer).
// Tile 16: self block, direct fp32 register->global stores (full-sector float2).
#define MM_AH 0
#define MM_B0 32768
#define MM_B1 65536
#define MSMEM 98304

__global__ __launch_bounds__(256, 2) void k_gemmM(int layer) {
    extern __shared__ char smem[];
    int t = threadIdx.x, lane = t & 31, w = t >> 5;
    int m0 = blockIdx.x * 128;
    uint32_t sbase = smem_u32(smem);
    const __half* Bh = g_Bh2[layer];

    prefetch_b(sbase + MM_B0, Bh, t);
    load_tile(smem + MM_AH, g_Ah, m0, t);

    int wm = (w & 1) * 64, wn = (w >> 1) * 32;
    int atile = lane >> 3, ar = lane & 7;
    int arow_base = wm + ((atile & 1) << 3) + ar;
    int achunk_sel = atile >> 1;
    int bl = lane & 15;
    int bhalf = bl >> 3, br = bl & 7;

    for (int n = 0; n < 17; n++) {
        uint32_t boff = (n & 1) ? MM_B1 : MM_B0;
        uint32_t bbase = sbase + boff;
        asm volatile("cp.async.wait_group 0;");
        __syncthreads();
        if (n + 1 < 17) {
            prefetch_b(sbase + (((n + 1) & 1) ? MM_B1 : MM_B0),
                       Bh + (size_t)(n + 1) * 128 * 128, t);
        }

        float acc[4][4][4];
#pragma unroll
        for (int i = 0; i < 4; i++)
#pragma unroll
            for (int j = 0; j < 4; j++)
#pragma unroll
                for (int q = 0; q < 4; q++) acc[i][j][q] = 0.0f;

#pragma unroll
        for (int ks = 0; ks < 8; ks++) {
            uint32_t a[4][4];
            uint32_t b[4][2];
            int ac = ks * 2 + achunk_sel;
#pragma unroll
            for (int i = 0; i < 4; i++) {
                int row = arow_base + i * 16;
                ldm_x4(a[i][0], a[i][1], a[i][2], a[i][3],
                       sbase + MM_AH + row * 256 + ((ac ^ (row & 7)) * 16));
            }
            int bc = ks * 2 + bhalf;
#pragma unroll
            for (int j = 0; j < 4; j++) {
                int row = wn + j * 8 + br;
                ldm_x2(b[j][0], b[j][1], bbase + row * 256 + ((bc ^ (row & 7)) * 16));
            }
#pragma unroll
            for (int i = 0; i < 4; i++)
#pragma unroll
                for (int j = 0; j < 4; j++)
                    mma16816(acc[i][j], a[i][0], a[i][1], a[i][2], a[i][3], b[j][0], b[j][1]);
        }

        if (n < 16) {
            __syncthreads();   // all warps done reading B buffer; reuse as fp16 C staging
            char* cs = smem + boff;
#pragma unroll
            for (int i = 0; i < 4; i++) {
#pragma unroll
                for (int j = 0; j < 4; j++) {
                    int r = wm + i * 16 + (lane >> 2);
                    int cb = (wn + j * 8 + 2 * (lane & 3)) * 2;
                    uint32_t off0 = r * 256 + ((((cb >> 4) ^ (r & 7)) << 4) | (cb & 15));
                    uint32_t off1 = (r + 8) * 256 + ((((cb >> 4) ^ ((r + 8) & 7)) << 4) | (cb & 15));
                    *(__half2*)(cs + off0) = __floats2half2_rn(acc[i][j][0], acc[i][j][1]);
                    *(__half2*)(cs + off1) = __floats2half2_rn(acc[i][j][2], acc[i][j][3]);
                }
            }
            __syncthreads();
#pragma unroll
            for (int it = 0; it < 8; it++) {
                int idx = it * 256 + t;            // 2048 chunks: 128 rows x 16 x 16B
                int row = idx >> 4, ch = idx & 15;
                uint4 v = *(const uint4*)(cs + row * 256 + ((ch ^ (row & 7)) << 4));
                *(uint4*)(g_trans16 + (size_t)(m0 + row) * 2048 + n * 128 + ch * 8) = v;
            }
            __syncthreads();   // readout done before this buffer is prefetched again
        } else {
            // self tile: direct fp32 stores, full 32B sectors (4 lanes x float2)
#pragma unroll
            for (int i = 0; i < 4; i++) {
#pragma unroll
                for (int j = 0; j < 4; j++) {
                    int r = wm + i * 16 + (lane >> 2);
                    int c = wn + j * 8 + 2 * (lane & 3);
                    *(float2*)(g_self + (size_t)(m0 + r) * 128 + c) =
                        make_float2(acc[i][j][0], acc[i][j][1]);
                    *(float2*)(g_self + (size_t)(m0 + r + 8) * 128 + c) =
                        make_float2(acc[i][j][2], acc[i][j][3]);
                }
            }
        }
    }
}

// ---------------- fused gather + update: warp per node, half-warp per edge ----------------
__device__ __forceinline__ void acc8(float* a, uint4 r) {
    float2 f;
    f = __half22float2(u32_as_h2(r.x)); a[0] += f.x; a[1] += f.y;
    f = __half22float2(u32_as_h2(r.y)); a[2] += f.x; a[3] += f.y;
    f = __half22float2(u32_as_h2(r.z)); a[4] += f.x; a[5] += f.y;
    f = __half22float2(u32_as_h2(r.w)); a[6] += f.x; a[7] += f.y;
}
__device__ __forceinline__ uint4 ldg_msg(const __half* p) {
    return __ldg((const uint4*)p);
}

__global__ __launch_bounds__(256) void k_gather(const float* __restrict__ bself,
                                                const float* __restrict__ lg,
                                                const float* __restrict__ lb,
                                                float* __restrict__ enc_out,
                                                int layer, int M) {
    int n = blockIdx.x * 8 + (threadIdx.x >> 5);
    int lane = threadIdx.x & 31;
    if (n >= M) return;
    int half = lane >> 4, hl = lane & 15;
    int beg = g_off[n], end = g_off[n + 1];

    float acc[8];
#pragma unroll
    for (int q = 0; q < 8; q++) acc[q] = 0.0f;

    int e = beg + half;
    for (; e + 6 < end; e += 8) {
        uint32_t p0 = g_sed[e], p1 = g_sed[e + 2], p2 = g_sed[e + 4], p3 = g_sed[e + 6];
        uint4 r0 = ldg_msg(g_trans16 + (size_t)(p0 & 0xFFFF) * 2048 + ((p0 >> 16) << 7) + hl * 8);
        uint4 r1 = ldg_msg(g_trans16 + (size_t)(p1 & 0xFFFF) * 2048 + ((p1 >> 16) << 7) + hl * 8);
        uint4 r2 = ldg_msg(g_trans16 + (size_t)(p2 & 0xFFFF) * 2048 + ((p2 >> 16) << 7) + hl * 8);
        uint4 r3 = ldg_msg(g_trans16 + (size_t)(p3 & 0xFFFF) * 2048 + ((p3 >> 16) << 7) + hl * 8);
        acc8(acc, r0); acc8(acc, r1); acc8(acc, r2); acc8(acc, r3);
    }
    for (; e < end; e += 2) {
        uint32_t p = g_sed[e];
        uint4 r = ldg_msg(g_trans16 + (size_t)(p & 0xFFFF) * 2048 + ((p >> 16) << 7) + hl * 8);
        acc8(acc, r);
    }
#pragma unroll
    for (int q = 0; q < 8; q++) acc[q] += __shfl_xor_sync(0xFFFFFFFFu, acc[q], 16);

    float inv = 1.0f / fmaxf((float)(end - beg), 1.0f);
    float4 s0 = *(const float4*)(g_self + (size_t)n * 128 + hl * 8);
    float4 s1 = *(const float4*)(g_self + (size_t)n * 128 + hl * 8 + 4);
    float4 b0 = *(const float4*)(bself + hl * 8);
    float4 b1 = *(const float4*)(bself + hl * 8 + 4);
    float v[8];
    v[0] = fmaxf(s0.x + b0.x + acc[0] * inv, 0.f);
    v[1] = fmaxf(s0.y + b0.y + acc[1] * inv, 0.f);
    v[2] = fmaxf(s0.z + b0.z + acc[2] * inv, 0.f);
    v[3] = fmaxf(s0.w + b0.w + acc[3] * inv, 0.f);
    v[4] = fmaxf(s1.x + b1.x + acc[4] * inv, 0.f);
    v[5] = fmaxf(s1.y + b1.y + acc[5] * inv, 0.f);
    v[6] = fmaxf(s1.z + b1.z + acc[6] * inv, 0.f);
    v[7] = fmaxf(s1.w + b1.w + acc[7] * inv, 0.f);

    float s = 0.f;
#pragma unroll
    for (int q = 0; q < 8; q++) s += v[q];
#pragma unroll
    for (int o = 1; o < 16; o <<= 1) s += __shfl_xor_sync(0xFFFFFFFFu, s, o);
    float mu = s * (1.0f / 128.0f);
    float qs = 0.f;
    float dv[8];
#pragma unroll
    for (int q = 0; q < 8; q++) { dv[q] = v[q] - mu; qs += dv[q] * dv[q]; }
#pragma unroll
    for (int o = 1; o < 16; o <<= 1) qs += __shfl_xor_sync(0xFFFFFFFFu, qs, o);
    float rstd = rsqrtf(qs * (1.0f / 128.0f) + 1e-5f);

    float4 g0 = *(const float4*)(lg + hl * 8);
    float4 g1 = *(const float4*)(lg + hl * 8 + 4);
    float4 p0 = *(const float4*)(lb + hl * 8);
    float4 p1 = *(const float4*)(lb + hl * 8 + 4);
    float ov[8];
    ov[0] = dv[0] * rstd * g0.x + p0.x; ov[1] = dv[1] * rstd * g0.y + p0.y;
    ov[2] = dv[2] * rstd * g0.z + p0.z; ov[3] = dv[3] * rstd * g0.w + p0.w;
    ov[4] = dv[4] * rstd * g1.x + p1.x; ov[5] = dv[5] * rstd * g1.y + p1.y;
    ov[6] = dv[6] * rstd * g1.z + p1.z; ov[7] = dv[7] * rstd * g1.w + p1.w;

    if (half == 0) {
        if (layer == 0) {
            __half2 h0 = __floats2half2_rn(ov[0], ov[1]);
            __half2 h1 = __floats2half2_rn(ov[2], ov[3]);
            __half2 h2 = __floats2half2_rn(ov[4], ov[5]);
            __half2 h3 = __floats2half2_rn(ov[6], ov[7]);
            float2 f0 = __half22float2(h0), f1 = __half22float2(h1);
            float2 f2 = __half22float2(h2), f3 = __half22float2(h3);
            __half2 l0 = __floats2half2_rn(ov[0] - f0.x, ov[1] - f0.y);
            __half2 l1 = __floats2half2_rn(ov[2] - f1.x, ov[3] - f1.y);
            __half2 l2 = __floats2half2_rn(ov[4] - f2.x, ov[5] - f2.y);
            __half2 l3 = __floats2half2_rn(ov[6] - f3.x, ov[7] - f3.y);
            *(uint4*)(g_Ah + (size_t)n * 128 + hl * 8) =
                make_uint4(h2_as_u32(h0), h2_as_u32(h1), h2_as_u32(h2), h2_as_u32(h3));
            *(uint4*)(g_Al + (size_t)n * 128 + hl * 8) =
                make_uint4(h2_as_u32(l0), h2_as_u32(l1), h2_as_u32(l2), h2_as_u32(l3));
        } else {
            *(float4*)(enc_out + (size_t)n * 128 + hl * 8) =
                make_float4(ov[0], ov[1], ov[2], ov[3]);
            *(float4*)(enc_out + (size_t)n * 128 + hl * 8 + 4) =
                make_float4(ov[4], ov[5], ov[6], ov[7]);
        }
    }
}

__global__ void k_wt(const float* __restrict__ Wih_f, const float* __restrict__ Whh_f,
                     const float* __restrict__ Wih_b, const float* __restrict__ Whh_b) {
    int idx = blockIdx.x * blockDim.x + threadIdx.x;
    if (idx >= 2 * 384 * 512) return;
    int dir = idx / (384 * 512);
    int rem = idx % (384 * 512);
    int d = rem / 512, j = rem % 512;
    const float* Wih = dir ? Wih_b : Wih_f;
    const float* Whh = dir ? Whh_b : Whh_f;
    float v = (d < 256) ? Wih[j * 256 + d] : Whh[j * 128 + (d - 256)];
    g_WT[dir][rem] = v;
}

// ---------------- LSTM input projection (seq build fused in) ----------------
__global__ __launch_bounds__(512) void k_xgate(const float* __restrict__ enc,
                                               const int* __restrict__ pn,
                                               const int* __restrict__ pr,
                                               const float* __restrict__ rel,
                                               const float* __restrict__ bf,
                                               const float* __restrict__ bb) {
    __shared__ float xt[256];
    int pl = blockIdx.x;               // p*4 + t
    int p = pl >> 2, tt = pl & 3;
    int dir = blockIdx.y;
    int j = threadIdx.x;
    const float* WT = g_WT[dir];
    const float* bias = dir ? bb : bf;
    if (j < 128) {
        int node = pn[p * 4 + tt];
        xt[j] = enc[(size_t)node * 128 + j];
    } else if (j < 256) {
        int d = j - 128;
        float rv = 0.0f;
        if (tt > 0) { int r = pr[p * 3 + (tt - 1)]; rv = rel[r * 128 + d]; }
        xt[j] = rv;
    }
    __syncthreads();
    float acc = bias[j];
    for (int d = 0; d < 256; d++) acc = fmaf(WT[d * 512 + j], xt[d], acc);
    g_gx[((size_t)dir * 1024 + pl) * 512 + j] = acc;
}

// ---------------- bidirectional LSTM: recurrent part only (K=128) ----------------
__global__ __launch_bounds__(512) void k_lstm() {
    const int PB = 8;
    __shared__ float hs[PB][128];
    __shared__ float cs[PB][128];
    __shared__ float gs[PB][512];
    int dir = blockIdx.y;
    const float* WT = g_WT[dir];
    int p0 = blockIdx.x * PB;
    int t = threadIdx.x;

    for (int i = t; i < PB * 128; i += 512) { ((float*)hs)[i] = 0.0f; ((float*)cs)[i] = 0.0f; }
    __syncthreads();

    for (int step = 0; step < 4; step++) {
        int tt = dir ? (3 - step) : step;
        float acc[PB];
#pragma unroll
        for (int p = 0; p < PB; p++)
            acc[p] = g_gx[((size_t)dir * 1024 + (p0 + p) * 4 + tt) * 512 + t];
        for (int d = 0; d < 128; d++) {
            float w = WT[(256 + d) * 512 + t];
#pragma unroll
            for (int p = 0; p < PB; p++) acc[p] = fmaf(w, hs[p][d], acc[p]);
        }
#pragma unroll
        for (int p = 0; p < PB; p++) gs[p][t] = acc[p];
        __syncthreads();
        for (int i = t; i < PB * 128; i += 512) {
            int pp = i >> 7, k = i & 127;
            float ig = 1.0f / (1.0f + expf(-gs[pp][k]));
            float fg = 1.0f / (1.0f + expf(-gs[pp][128 + k]));
            float gg = tanhf(gs[pp][256 + k]);
            float og = 1.0f / (1.0f + expf(-gs[pp][384 + k]));
            float c = fg * cs[pp][k] + ig * gg;
            cs[pp][k] = c;
            hs[pp][k] = og * tanhf(c);
        }
        __syncthreads();
    }
    for (int i = t; i < PB * 128; i += 512) {
        int pp = i >> 7, k = i & 127;
        g_h[((size_t)dir * 256 + p0 + pp) * 128 + k] = hs[pp][k];
    }
}

// ---------------- output head ----------------
__global__ void k_head(const float* __restrict__ Wop, const float* __restrict__ bop,
                       const float* __restrict__ q, const float* __restrict__ Ws1,
                       const float* __restrict__ bs1, const float* __restrict__ Ws2,
                       const float* __restrict__ bs2,
                       float* __restrict__ pe_out, float* __restrict__ sim_out) {
    int p = blockIdx.x;
    int k = threadIdx.x;
    __shared__ float cat[256];
    __shared__ float cat2[256];
    __shared__ float red[4];
    cat[k]       = g_h[(size_t)p * 128 + k];
    cat[128 + k] = g_h[(size_t)(256 + p) * 128 + k];
    __syncthreads();
    float acc = bop[k];
    for (int j = 0; j < 256; j++) acc = fmaf(cat[j], Wop[k * 256 + j], acc);
    float pe = fmaxf(acc, 0.0f);
    pe_out[(size_t)p * 128 + k] = pe;
    cat2[k] = pe;
    cat2[128 + k] = q[k];
    __syncthreads();
    float a2 = bs1[k];
    for (int j = 0; j < 256; j++) a2 = fmaf(cat2[j], Ws1[k * 256 + j], a2);
    float hdn = fmaxf(a2, 0.0f);
    float s = hdn * Ws2[k];
#pragma unroll
    for (int o = 16; o > 0; o >>= 1) s += __shfl_xor_sync(0xFFFFFFFFu, s, o);
    if ((k & 31) == 0) red[k >> 5] = s;
    __syncthreads();
    if (k == 0) {
        float tot = red[0] + red[1] + red[2] + red[3] + bs2[0];
        sim_out[p] = 1.0f / (1.0f + expf(-tot));
    }
}

// ---------------- launch ----------------
extern "C" void kernel_launch(void* const* d_in, const int* in_sizes, int n_in,
                              void* d_out, int out_size) {
    const float* node_features = (const float*)d_in[0];
    const int*   edge_index    = (const int*)d_in[1];
    const int*   edge_types    = (const int*)d_in[2];
    const float* query         = (const float*)d_in[3];
    const int*   path_nodes    = (const int*)d_in[4];
    const int*   path_rel      = (const int*)d_in[5];
    const float* W_self        = (const float*)d_in[6];
    const float* b_self        = (const float*)d_in[7];
    const float* W_rel         = (const float*)d_in[8];
    const float* ln_g          = (const float*)d_in[9];
    const float* ln_b          = (const float*)d_in[10];
    const float* rel_emb       = (const float*)d_in[11];
    const float* W_ih_f        = (const float*)d_in[12];
    const float* W_hh_f        = (const float*)d_in[13];
    const float* b_f           = (const float*)d_in[14];
    const float* W_ih_b        = (const float*)d_in[15];
    const float* W_hh_b        = (const float*)d_in[16];
    const float* b_b           = (const float*)d_in[17];
    const float* W_op          = (const float*)d_in[18];
    const float* b_op          = (const float*)d_in[19];
    const float* W_s1          = (const float*)d_in[20];
    const float* b_s1          = (const float*)d_in[21];
    const float* W_s2          = (const float*)d_in[22];
    const float* b_s2          = (const float*)d_in[23];
    (void)n_in; (void)out_size;

    const int N = in_sizes[0] / 128;
    const int E = in_sizes[1] / 2;
    const int P = in_sizes[4] / 4;

    float* out     = (float*)d_out;
    float* enc_out = out;
    float* pe_out  = out + (size_t)N * 128;
    float* sim_out = pe_out + (size_t)P * 128;

    const int* src = edge_index;
    const int* dst = edge_index + E;

    cudaFuncSetAttribute(k_gemmM, cudaFuncAttributeMaxDynamicSharedMemorySize, MSMEM);

    k_conv<<<(MPAD * 32 + 255) / 256, 256>>>(node_features, N);   // also zeroes g_cnt
    k_packb<<<(2 * NCOL * 128 + 255) / 256, 256>>>(W_rel, W_self);
    k_wt<<<(2 * 384 * 512 + 255) / 256, 256>>>(W_ih_f, W_hh_f, W_ih_b, W_hh_b);
    k_gemmM<<<MPAD / 128, 256, MSMEM>>>(0);

    k_hist<<<(E + 255) / 256, 256>>>(dst, E);
    k_scan<<<1, 1024>>>(N);
    k_place<<<(E + 255) / 256, 256>>>(src, dst, edge_types, E);

    k_gather<<<(N + 7) / 8, 256>>>(b_self, ln_g, ln_b, enc_out, 0, N);
    k_gemmM<<<MPAD / 128, 256, MSMEM>>>(1);
    k_gather<<<(N + 7) / 8, 256>>>(b_self + 128, ln_g + 128, ln_b + 128, enc_out, 1, N);

    k_xgate<<<dim3(P * 4, 2), 512>>>(enc_out, path_nodes, path_rel, rel_emb, b_f, b_b);
    k_lstm<<<dim3(P / 8, 2), 512>>>();
    k_head<<<P, 128>>>(W_op, b_op, query, W_s1, b_s1, W_s2, b_s2, pe_out, sim_out);
}

// round 15
// speedup vs baseline: 1.8220x; 1.0063x over previous
#include <cuda_runtime.h>
#include <cuda_fp16.h>
#include <math.h>
#include <stdint.h>

#define D 128
#define R 16
#define NCOL 2176
#define MPAD 50048         // 391 * 128
#define NMAX 50000
#define EMAX 800000

// ---------------- scratch (device globals; allocation-free) ----------------
__device__ __half g_trans16[(size_t)MPAD * 2048];  // 204 MB, relation messages
__device__ float g_self[(size_t)MPAD * 128];
__device__ __half g_Ah[(size_t)MPAD * 128];
__device__ __half g_Al[(size_t)MPAD * 128];
__device__ __half g_Bh2[2][NCOL * 128];             // both layers packed upfront
__device__ float g_WT[2][384 * 512];
__device__ float g_gx[2 * 256 * 4 * 512];           // precomputed x-gates [dir][p*4+t][512]
__device__ float g_h[2 * 256 * 128];
// CSR
__device__ int g_cnt[NMAX];
__device__ int g_off[NMAX + 1];
__device__ int g_cur[NMAX];
__device__ uint32_t g_sed[EMAX];   // packed src | (r<<16)

// ---------------- bit-cast helpers ----------------
__device__ __forceinline__ uint32_t h2_as_u32(__half2 h) {
    uint32_t u; *(__half2*)&u = h; return u;
}
__device__ __forceinline__ __half2 u32_as_h2(uint32_t u) {
    __half2 h; *(uint32_t*)&h = u; return h;
}

// ---------------- PTX helpers ----------------
__device__ __forceinline__ uint32_t smem_u32(const void* p) {
    return (uint32_t)__cvta_generic_to_shared(p);
}
__device__ __forceinline__ void ldm_x4(uint32_t& r0, uint32_t& r1, uint32_t& r2, uint32_t& r3,
                                       uint32_t a) {
    asm volatile("ldmatrix.sync.aligned.m8n8.x4.shared.b16 {%0,%1,%2,%3}, [%4];"
                 : "=r"(r0), "=r"(r1), "=r"(r2), "=r"(r3) : "r"(a));
}
__device__ __forceinline__ void ldm_x2(uint32_t& r0, uint32_t& r1, uint32_t a) {
    asm volatile("ldmatrix.sync.aligned.m8n8.x2.shared.b16 {%0,%1}, [%2];"
                 : "=r"(r0), "=r"(r1) : "r"(a));
}
__device__ __forceinline__ void mma16816(float* c, uint32_t a0, uint32_t a1, uint32_t a2,
                                         uint32_t a3, uint32_t b0, uint32_t b1) {
    asm volatile(
        "mma.sync.aligned.m16n8k16.row.col.f32.f16.f16.f32 "
        "{%0,%1,%2,%3}, {%4,%5,%6,%7}, {%8,%9}, {%0,%1,%2,%3};"
        : "+f"(c[0]), "+f"(c[1]), "+f"(c[2]), "+f"(c[3])
        : "r"(a0), "r"(a1), "r"(a2), "r"(a3), "r"(b0), "r"(b1));
}
__device__ __forceinline__ void cpa16(uint32_t dst, const void* src) {
    asm volatile("cp.async.cg.shared.global [%0], [%1], 16;" :: "r"(dst), "l"(src));
}

// ---------------- CSR build ----------------
__global__ void k_zero_cnt(int N) {
    int i = blockIdx.x * blockDim.x + threadIdx.x;
    if (i < N) g_cnt[i] = 0;
}
__global__ void k_hist(const int* __restrict__ dst, int E) {
    int e = blockIdx.x * blockDim.x + threadIdx.x;
    if (e < E) atomicAdd(&g_cnt[dst[e]], 1);
}
__global__ __launch_bounds__(1024) void k_scan(int N) {
    __shared__ int sh[1024];
    int t = threadIdx.x;
    int chunk = (N + 1023) / 1024;
    int c0 = t * chunk, c1 = min(c0 + chunk, N);
    int s = 0;
    for (int i = c0; i < c1; i++) s += g_cnt[i];
    sh[t] = s;
    __syncthreads();
    for (int o = 1; o < 1024; o <<= 1) {
        int v = (t >= o) ? sh[t - o] : 0;
        __syncthreads();
        sh[t] += v;
        __syncthreads();
    }
    int run = sh[t] - s;
    for (int i = c0; i < c1; i++) {
        g_off[i] = run;
        g_cur[i] = run;
        run += g_cnt[i];
    }
    if (t == 1023) g_off[N] = run;
}
__global__ void k_place(const int* __restrict__ src, const int* __restrict__ dst,
                        const int* __restrict__ et, int E) {
    int e = blockIdx.x * blockDim.x + threadIdx.x;
    if (e >= E) return;
    int pos = atomicAdd(&g_cur[dst[e]], 1);
    g_sed[pos] = (uint32_t)src[e] | ((uint32_t)et[e] << 16);
}

// ---------------- conversions ----------------
__global__ void k_conv(const float* __restrict__ x0, int Nn) {
    int i4 = blockIdx.x * blockDim.x + threadIdx.x;
    if (i4 >= MPAD * 32) return;
    int row = i4 >> 5;
    float4 v = make_float4(0.f, 0.f, 0.f, 0.f);
    if (row < Nn) v = *(const float4*)(x0 + (size_t)i4 * 4);
    __half2 h0 = __floats2half2_rn(v.x, v.y);
    __half2 h1 = __floats2half2_rn(v.z, v.w);
    float2 f0 = __half22float2(h0), f1 = __half22float2(h1);
    __half2 l0 = __floats2half2_rn(v.x - f0.x, v.y - f0.y);
    __half2 l1 = __floats2half2_rn(v.z - f1.x, v.w - f1.y);
    ((uint2*)g_Ah)[i4] = make_uint2(h2_as_u32(h0), h2_as_u32(h1));
    ((uint2*)g_Al)[i4] = make_uint2(h2_as_u32(l0), h2_as_u32(l1));
}

__global__ void k_packb(const float* __restrict__ Wrel, const float* __restrict__ Wself) {
    int idx0 = blockIdx.x * blockDim.x + threadIdx.x;
    if (idx0 >= 2 * NCOL * 128) return;
    int l = idx0 / (NCOL * 128);
    int idx = idx0 % (NCOL * 128);
    int n = idx >> 7, d = idx & 127;
    const float* Wr = Wrel + (size_t)l * R * 128 * 128;
    const float* Ws = Wself + (size_t)l * 128 * 128;
    float v;
    if (n < 2048) {
        int r = n >> 7, k = n & 127;
        v = Wr[((size_t)r * 128 + d) * 128 + k];
    } else {
        v = Ws[d * 128 + (n - 2048)];
    }
    g_Bh2[l][idx] = __float2half_rn(v);
}

// ---------------- shared GEMM helpers ----------------
__device__ __forceinline__ void load_tile(char* dstbase, const __half* g, int row0, int t) {
#pragma unroll
    for (int it = 0; it < 8; it++) {
        int cl = it * 256 + t;
        int row = cl >> 4, c = cl & 15;
        uint4 v = *(const uint4*)(g + (size_t)(row0 + row) * 128 + c * 8);
        *(uint4*)(dstbase + row * 256 + ((c ^ (row & 7)) * 16)) = v;
    }
}

__device__ __forceinline__ void prefetch_b(uint32_t dstb, const __half* gsrc, int t) {
#pragma unroll
    for (int it = 0; it < 8; it++) {
        int cl = it * 256 + t;
        int row = cl >> 4, c = cl & 15;
        cpa16(dstb + row * 256 + ((c ^ (row & 7)) * 16), gsrc + (size_t)row * 128 + c * 8);
    }
    asm volatile("cp.async.commit_group;");
}

// ---------------- unified GEMM: 17 n-tiles, single pass, 2 CTAs/SM ----------------
#define MM_AH 0
#define MM_B0 32768
#define MM_B1 65536
#define MSMEM 98304

__global__ __launch_bounds__(256, 2) void k_gemmM(int layer) {
    extern __shared__ char smem[];
    int t = threadIdx.x, lane = t & 31, w = t >> 5;
    int m0 = blockIdx.x * 128;
    uint32_t sbase = smem_u32(smem);
    const __half* Bh = g_Bh2[layer];

    prefetch_b(sbase + MM_B0, Bh, t);
    load_tile(smem + MM_AH, g_Ah, m0, t);

    int wm = (w & 1) * 64, wn = (w >> 1) * 32;
    int atile = lane >> 3, ar = lane & 7;
    int arow_base = wm + ((atile & 1) << 3) + ar;
    int achunk_sel = atile >> 1;
    int bl = lane & 15;
    int bhalf = bl >> 3, br = bl & 7;

    for (int n = 0; n < 17; n++) {
        uint32_t boff = (n & 1) ? MM_B1 : MM_B0;
        uint32_t bbase = sbase + boff;
        asm volatile("cp.async.wait_group 0;");
        __syncthreads();
        if (n + 1 < 17) {
            prefetch_b(sbase + (((n + 1) & 1) ? MM_B1 : MM_B0),
                       Bh + (size_t)(n + 1) * 128 * 128, t);
        }

        float acc[4][4][4];
#pragma unroll
        for (int i = 0; i < 4; i++)
#pragma unroll
            for (int j = 0; j < 4; j++)
#pragma unroll
                for (int q = 0; q < 4; q++) acc[i][j][q] = 0.0f;

#pragma unroll
        for (int ks = 0; ks < 8; ks++) {
            uint32_t a[4][4];
            uint32_t b[4][2];
            int ac = ks * 2 + achunk_sel;
#pragma unroll
            for (int i = 0; i < 4; i++) {
                int row = arow_base + i * 16;
                ldm_x4(a[i][0], a[i][1], a[i][2], a[i][3],
                       sbase + MM_AH + row * 256 + ((ac ^ (row & 7)) * 16));
            }
            int bc = ks * 2 + bhalf;
#pragma unroll
            for (int j = 0; j < 4; j++) {
                int row = wn + j * 8 + br;
                ldm_x2(b[j][0], b[j][1], bbase + row * 256 + ((bc ^ (row & 7)) * 16));
            }
#pragma unroll
            for (int i = 0; i < 4; i++)
#pragma unroll
                for (int j = 0; j < 4; j++)
                    mma16816(acc[i][j], a[i][0], a[i][1], a[i][2], a[i][3], b[j][0], b[j][1]);
        }

        if (n < 16) {
            __syncthreads();   // all warps done reading B buffer; reuse as fp16 C staging
            char* cs = smem + boff;
#pragma unroll
            for (int i = 0; i < 4; i++) {
#pragma unroll
                for (int j = 0; j < 4; j++) {
                    int r = wm + i * 16 + (lane >> 2);
                    int cb = (wn + j * 8 + 2 * (lane & 3)) * 2;
                    uint32_t off0 = r * 256 + ((((cb >> 4) ^ (r & 7)) << 4) | (cb & 15));
                    uint32_t off1 = (r + 8) * 256 + ((((cb >> 4) ^ ((r + 8) & 7)) << 4) | (cb & 15));
                    *(__half2*)(cs + off0) = __floats2half2_rn(acc[i][j][0], acc[i][j][1]);
                    *(__half2*)(cs + off1) = __floats2half2_rn(acc[i][j][2], acc[i][j][3]);
                }
            }
            __syncthreads();
#pragma unroll
            for (int it = 0; it < 8; it++) {
                int idx = it * 256 + t;            // 2048 chunks: 128 rows x 16 x 16B
                int row = idx >> 4, ch = idx & 15;
                uint4 v = *(const uint4*)(cs + row * 256 + ((ch ^ (row & 7)) << 4));
                *(uint4*)(g_trans16 + (size_t)(m0 + row) * 2048 + n * 128 + ch * 8) = v;
            }
            __syncthreads();   // readout done before this buffer is prefetched again
        } else {
            // self tile: direct fp32 stores, full 32B sectors (4 lanes x float2)
#pragma unroll
            for (int i = 0; i < 4; i++) {
#pragma unroll
                for (int j = 0; j < 4; j++) {
                    int r = wm + i * 16 + (lane >> 2);
                    int c = wn + j * 8 + 2 * (lane & 3);
                    *(float2*)(g_self + (size_t)(m0 + r) * 128 + c) =
                        make_float2(acc[i][j][0], acc[i][j][1]);
                    *(float2*)(g_self + (size_t)(m0 + r + 8) * 128 + c) =
                        make_float2(acc[i][j][2], acc[i][j][3]);
                }
            }
        }
    }
}

// ---------------- fused gather + update: warp per node, half-warp per edge ----------------
__device__ __forceinline__ void acc8(float* a, uint4 r) {
    float2 f;
    f = __half22float2(u32_as_h2(r.x)); a[0] += f.x; a[1] += f.y;
    f = __half22float2(u32_as_h2(r.y)); a[2] += f.x; a[3] += f.y;
    f = __half22float2(u32_as_h2(r.z)); a[4] += f.x; a[5] += f.y;
    f = __half22float2(u32_as_h2(r.w)); a[6] += f.x; a[7] += f.y;
}
__device__ __forceinline__ uint4 ldg_msg(const __half* p) {
    return __ldg((const uint4*)p);
}

__global__ __launch_bounds__(256) void k_gather(const float* __restrict__ bself,
                                                const float* __restrict__ lg,
                                                const float* __restrict__ lb,
                                                float* __restrict__ enc_out,
                                                int layer, int M) {
    int n = blockIdx.x * 8 + (threadIdx.x >> 5);
    int lane = threadIdx.x & 31;
    if (n >= M) return;
    int half = lane >> 4, hl = lane & 15;
    int beg = g_off[n], end = g_off[n + 1];

    float acc[8];
#pragma unroll
    for (int q = 0; q < 8; q++) acc[q] = 0.0f;

    int e = beg + half;
    for (; e + 6 < end; e += 8) {
        uint32_t p0 = g_sed[e], p1 = g_sed[e + 2], p2 = g_sed[e + 4], p3 = g_sed[e + 6];
        uint4 r0 = ldg_msg(g_trans16 + (size_t)(p0 & 0xFFFF) * 2048 + ((p0 >> 16) << 7) + hl * 8);
        uint4 r1 = ldg_msg(g_trans16 + (size_t)(p1 & 0xFFFF) * 2048 + ((p1 >> 16) << 7) + hl * 8);
        uint4 r2 = ldg_msg(g_trans16 + (size_t)(p2 & 0xFFFF) * 2048 + ((p2 >> 16) << 7) + hl * 8);
        uint4 r3 = ldg_msg(g_trans16 + (size_t)(p3 & 0xFFFF) * 2048 + ((p3 >> 16) << 7) + hl * 8);
        acc8(acc, r0); acc8(acc, r1); acc8(acc, r2); acc8(acc, r3);
    }
    for (; e < end; e += 2) {
        uint32_t p = g_sed[e];
        uint4 r = ldg_msg(g_trans16 + (size_t)(p & 0xFFFF) * 2048 + ((p >> 16) << 7) + hl * 8);
        acc8(acc, r);
    }
#pragma unroll
    for (int q = 0; q < 8; q++) acc[q] += __shfl_xor_sync(0xFFFFFFFFu, acc[q], 16);

    float inv = 1.0f / fmaxf((float)(end - beg), 1.0f);
    float4 s0 = *(const float4*)(g_self + (size_t)n * 128 + hl * 8);
    float4 s1 = *(const float4*)(g_self + (size_t)n * 128 + hl * 8 + 4);
    float4 b0 = *(const float4*)(bself + hl * 8);
    float4 b1 = *(const float4*)(bself + hl * 8 + 4);
    float v[8];
    v[0] = fmaxf(s0.x + b0.x + acc[0] * inv, 0.f);
    v[1] = fmaxf(s0.y + b0.y + acc[1] * inv, 0.f);
    v[2] = fmaxf(s0.z + b0.z + acc[2] * inv, 0.f);
    v[3] = fmaxf(s0.w + b0.w + acc[3] * inv, 0.f);
    v[4] = fmaxf(s1.x + b1.x + acc[4] * inv, 0.f);
    v[5] = fmaxf(s1.y + b1.y + acc[5] * inv, 0.f);
    v[6] = fmaxf(s1.z + b1.z + acc[6] * inv, 0.f);
    v[7] = fmaxf(s1.w + b1.w + acc[7] * inv, 0.f);

    float s = 0.f;
#pragma unroll
    for (int q = 0; q < 8; q++) s += v[q];
#pragma unroll
    for (int o = 1; o < 16; o <<= 1) s += __shfl_xor_sync(0xFFFFFFFFu, s, o);
    float mu = s * (1.0f / 128.0f);
    float qs = 0.f;
    float dv[8];
#pragma unroll
    for (int q = 0; q < 8; q++) { dv[q] = v[q] - mu; qs += dv[q] * dv[q]; }
#pragma unroll
    for (int o = 1; o < 16; o <<= 1) qs += __shfl_xor_sync(0xFFFFFFFFu, qs, o);
    float rstd = rsqrtf(qs * (1.0f / 128.0f) + 1e-5f);

    float4 g0 = *(const float4*)(lg + hl * 8);
    float4 g1 = *(const float4*)(lg + hl * 8 + 4);
    float4 p0 = *(const float4*)(lb + hl * 8);
    float4 p1 = *(const float4*)(lb + hl * 8 + 4);
    float ov[8];
    ov[0] = dv[0] * rstd * g0.x + p0.x; ov[1] = dv[1] * rstd * g0.y + p0.y;
    ov[2] = dv[2] * rstd * g0.z + p0.z; ov[3] = dv[3] * rstd * g0.w + p0.w;
    ov[4] = dv[4] * rstd * g1.x + p1.x; ov[5] = dv[5] * rstd * g1.y + p1.y;
    ov[6] = dv[6] * rstd * g1.z + p1.z; ov[7] = dv[7] * rstd * g1.w + p1.w;

    if (half == 0) {
        if (layer == 0) {
            __half2 h0 = __floats2half2_rn(ov[0], ov[1]);
            __half2 h1 = __floats2half2_rn(ov[2], ov[3]);
            __half2 h2 = __floats2half2_rn(ov[4], ov[5]);
            __half2 h3 = __floats2half2_rn(ov[6], ov[7]);
            float2 f0 = __half22float2(h0), f1 = __half22float2(h1);
            float2 f2 = __half22float2(h2), f3 = __half22float2(h3);
            __half2 l0 = __floats2half2_rn(ov[0] - f0.x, ov[1] - f0.y);
            __half2 l1 = __floats2half2_rn(ov[2] - f1.x, ov[3] - f1.y);
            __half2 l2 = __floats2half2_rn(ov[4] - f2.x, ov[5] - f2.y);
            __half2 l3 = __floats2half2_rn(ov[6] - f3.x, ov[7] - f3.y);
            *(uint4*)(g_Ah + (size_t)n * 128 + hl * 8) =
                make_uint4(h2_as_u32(h0), h2_as_u32(h1), h2_as_u32(h2), h2_as_u32(h3));
            *(uint4*)(g_Al + (size_t)n * 128 + hl * 8) =
                make_uint4(h2_as_u32(l0), h2_as_u32(l1), h2_as_u32(l2), h2_as_u32(l3));
        } else {
            *(float4*)(enc_out + (size_t)n * 128 + hl * 8) =
                make_float4(ov[0], ov[1], ov[2], ov[3]);
            *(float4*)(enc_out + (size_t)n * 128 + hl * 8 + 4) =
                make_float4(ov[4], ov[5], ov[6], ov[7]);
        }
    }
}

__global__ void k_wt(const float* __restrict__ Wih_f, const float* __restrict__ Whh_f,
                     const float* __restrict__ Wih_b, const float* __restrict__ Whh_b) {
    int idx = blockIdx.x * blockDim.x + threadIdx.x;
    if (idx >= 2 * 384 * 512) return;
    int dir = idx / (384 * 512);
    int rem = idx % (384 * 512);
    int d = rem / 512, j = rem % 512;
    const float* Wih = dir ? Wih_b : Wih_f;
    const float* Whh = dir ? Whh_b : Whh_f;
    float v = (d < 256) ? Wih[j * 256 + d] : Whh[j * 128 + (d - 256)];
    g_WT[dir][rem] = v;
}

// ---------------- LSTM input projection (seq build fused in) ----------------
__global__ __launch_bounds__(512) void k_xgate(const float* __restrict__ enc,
                                               const int* __restrict__ pn,
                                               const int* __restrict__ pr,
                                               const float* __restrict__ rel,
                                               const float* __restrict__ bf,
                                               const float* __restrict__ bb) {
    __shared__ float xt[256];
    int pl = blockIdx.x;               // p*4 + t
    int p = pl >> 2, tt = pl & 3;
    int dir = blockIdx.y;
    int j = threadIdx.x;
    const float* WT = g_WT[dir];
    const float* bias = dir ? bb : bf;
    if (j < 128) {
        int node = pn[p * 4 + tt];
        xt[j] = enc[(size_t)node * 128 + j];
    } else if (j < 256) {
        int d = j - 128;
        float rv = 0.0f;
        if (tt > 0) { int r = pr[p * 3 + (tt - 1)]; rv = rel[r * 128 + d]; }
        xt[j] = rv;
    }
    __syncthreads();
    float acc = bias[j];
    for (int d = 0; d < 256; d++) acc = fmaf(WT[d * 512 + j], xt[d], acc);
    g_gx[((size_t)dir * 1024 + pl) * 512 + j] = acc;
}

// ---------------- bidirectional LSTM: recurrent part only (K=128) ----------------
__global__ __launch_bounds__(512) void k_lstm() {
    const int PB = 8;
    __shared__ float hs[PB][128];
    __shared__ float cs[PB][128];
    __shared__ float gs[PB][512];
    int dir = blockIdx.y;
    const float* WT = g_WT[dir];
    int p0 = blockIdx.x * PB;
    int t = threadIdx.x;

    for (int i = t; i < PB * 128; i += 512) { ((float*)hs)[i] = 0.0f; ((float*)cs)[i] = 0.0f; }
    __syncthreads();

    for (int step = 0; step < 4; step++) {
        int tt = dir ? (3 - step) : step;
        float acc[PB];
#pragma unroll
        for (int p = 0; p < PB; p++)
            acc[p] = g_gx[((size_t)dir * 1024 + (p0 + p) * 4 + tt) * 512 + t];
        for (int d = 0; d < 128; d++) {
            float w = WT[(256 + d) * 512 + t];
#pragma unroll
            for (int p = 0; p < PB; p++) acc[p] = fmaf(w, hs[p][d], acc[p]);
        }
#pragma unroll
        for (int p = 0; p < PB; p++) gs[p][t] = acc[p];
        __syncthreads();
        for (int i = t; i < PB * 128; i += 512) {
            int pp = i >> 7, k = i & 127;
            float ig = 1.0f / (1.0f + expf(-gs[pp][k]));
            float fg = 1.0f / (1.0f + expf(-gs[pp][128 + k]));
            float gg = tanhf(gs[pp][256 + k]);
            float og = 1.0f / (1.0f + expf(-gs[pp][384 + k]));
            float c = fg * cs[pp][k] + ig * gg;
            cs[pp][k] = c;
            hs[pp][k] = og * tanhf(c);
        }
        __syncthreads();
    }
    for (int i = t; i < PB * 128; i += 512) {
        int pp = i >> 7, k = i & 127;
        g_h[((size_t)dir * 256 + p0 + pp) * 128 + k] = hs[pp][k];
    }
}

// ---------------- output head ----------------
__global__ void k_head(const float* __restrict__ Wop, const float* __restrict__ bop,
                       const float* __restrict__ q, const float* __restrict__ Ws1,
                       const float* __restrict__ bs1, const float* __restrict__ Ws2,
                       const float* __restrict__ bs2,
                       float* __restrict__ pe_out, float* __restrict__ sim_out) {
    int p = blockIdx.x;
    int k = threadIdx.x;
    __shared__ float cat[256];
    __shared__ float cat2[256];
    __shared__ float red[4];
    cat[k]       = g_h[(size_t)p * 128 + k];
    cat[128 + k] = g_h[(size_t)(256 + p) * 128 + k];
    __syncthreads();
    float acc = bop[k];
    for (int j = 0; j < 256; j++) acc = fmaf(cat[j], Wop[k * 256 + j], acc);
    float pe = fmaxf(acc, 0.0f);
    pe_out[(size_t)p * 128 + k] = pe;
    cat2[k] = pe;
    cat2[128 + k] = q[k];
    __syncthreads();
    float a2 = bs1[k];
    for (int j = 0; j < 256; j++) a2 = fmaf(cat2[j], Ws1[k * 256 + j], a2);
    float hdn = fmaxf(a2, 0.0f);
    float s = hdn * Ws2[k];
#pragma unroll
    for (int o = 16; o > 0; o >>= 1) s += __shfl_xor_sync(0xFFFFFFFFu, s, o);
    if ((k & 31) == 0) red[k >> 5] = s;
    __syncthreads();
    if (k == 0) {
        float tot = red[0] + red[1] + red[2] + red[3] + bs2[0];
        sim_out[p] = 1.0f / (1.0f + expf(-tot));
    }
}

// ---------------- launch ----------------
extern "C" void kernel_launch(void* const* d_in, const int* in_sizes, int n_in,
                              void* d_out, int out_size) {
    const float* node_features = (const float*)d_in[0];
    const int*   edge_index    = (const int*)d_in[1];
    const int*   edge_types    = (const int*)d_in[2];
    const float* query         = (const float*)d_in[3];
    const int*   path_nodes    = (const int*)d_in[4];
    const int*   path_rel      = (const int*)d_in[5];
    const float* W_self        = (const float*)d_in[6];
    const float* b_self        = (const float*)d_in[7];
    const float* W_rel         = (const float*)d_in[8];
    const float* ln_g          = (const float*)d_in[9];
    const float* ln_b          = (const float*)d_in[10];
    const float* rel_emb       = (const float*)d_in[11];
    const float* W_ih_f        = (const float*)d_in[12];
    const float* W_hh_f        = (const float*)d_in[13];
    const float* b_f           = (const float*)d_in[14];
    const float* W_ih_b        = (const float*)d_in[15];
    const float* W_hh_b        = (const float*)d_in[16];
    const float* b_b           = (const float*)d_in[17];
    const float* W_op          = (const float*)d_in[18];
    const float* b_op          = (const float*)d_in[19];
    const float* W_s1          = (const float*)d_in[20];
    const float* b_s1          = (const float*)d_in[21];
    const float* W_s2          = (const float*)d_in[22];
    const float* b_s2          = (const float*)d_in[23];
    (void)n_in; (void)out_size;

    const int N = in_sizes[0] / 128;
    const int E = in_sizes[1] / 2;
    const int P = in_sizes[4] / 4;

    float* out     = (float*)d_out;
    float* enc_out = out;
    float* pe_out  = out + (size_t)N * 128;
    float* sim_out = pe_out + (size_t)P * 128;

    const int* src = edge_index;
    const int* dst = edge_index + E;

    // one-time resources (created on the correctness call, before graph capture)
    static cudaStream_t s1 = nullptr;
    static cudaEvent_t e0 = nullptr, e1 = nullptr, e2 = nullptr;
    if (s1 == nullptr) {
        cudaStreamCreateWithFlags(&s1, cudaStreamNonBlocking);
        cudaEventCreateWithFlags(&e0, cudaEventDisableTiming);
        cudaEventCreateWithFlags(&e1, cudaEventDisableTiming);
        cudaEventCreateWithFlags(&e2, cudaEventDisableTiming);
        cudaFuncSetAttribute(k_gemmM, cudaFuncAttributeMaxDynamicSharedMemorySize, MSMEM);
    }

    // fork: side stream does weight packing + CSR build + LSTM weight transpose
    cudaEventRecord(e0, 0);
    cudaStreamWaitEvent(s1, e0, 0);

    k_packb<<<(2 * NCOL * 128 + 255) / 256, 256, 0, s1>>>(W_rel, W_self);
    cudaEventRecord(e1, s1);                            // packb done (gemm0 dep)
    k_zero_cnt<<<(N + 255) / 256, 256, 0, s1>>>(N);
    k_hist<<<(E + 255) / 256, 256, 0, s1>>>(dst, E);
    k_scan<<<1, 1024, 0, s1>>>(N);
    k_place<<<(E + 255) / 256, 256, 0, s1>>>(src, dst, edge_types, E);
    k_wt<<<(2 * 384 * 512 + 255) / 256, 256, 0, s1>>>(W_ih_f, W_hh_f, W_ih_b, W_hh_b);
    cudaEventRecord(e2, s1);                            // CSR + wt done (gather0/xgate dep)

    // main stream
    k_conv<<<(MPAD * 32 + 255) / 256, 256>>>(node_features, N);
    cudaStreamWaitEvent(0, e1, 0);
    k_gemmM<<<MPAD / 128, 256, MSMEM>>>(0);
    cudaStreamWaitEvent(0, e2, 0);
    k_gather<<<(N + 7) / 8, 256>>>(b_self, ln_g, ln_b, enc_out, 0, N);
    k_gemmM<<<MPAD / 128, 256, MSMEM>>>(1);
    k_gather<<<(N + 7) / 8, 256>>>(b_self + 128, ln_g + 128, ln_b + 128, enc_out, 1, N);

    k_xgate<<<dim3(P * 4, 2), 512>>>(enc_out, path_nodes, path_rel, rel_emb, b_f, b_b);
    k_lstm<<<dim3(P / 8, 2), 512>>>();
    k_head<<<P, 128>>>(W_op, b_op, query, W_s1, b_s1, W_s2, b_s2, pe_out, sim_out);
}

// round 16
// speedup vs baseline: 1.9703x; 1.0814x over previous
#include <cuda_runtime.h>
#include <cuda_fp16.h>
#include <math.h>
#include <stdint.h>

#define D 128
#define R 16
#define NCOL 2176
#define MPAD 50048         // 391 * 128
#define NMAX 50000
#define EMAX 800000
#define HSPLIT 25088       // 196 tiles * 128 rows

// ---------------- scratch (device globals; allocation-free) ----------------
__device__ __half g_trans16[2][(size_t)MPAD * 2048]; // per-layer message buffers
__device__ float g_self[2][(size_t)MPAD * 128];
__device__ __half g_Ah[(size_t)MPAD * 128];
__device__ __half g_Al[(size_t)MPAD * 128];
__device__ __half g_Bh2[2][NCOL * 128];
__device__ float g_WT[2][384 * 512];
__device__ float g_gx[2 * 256 * 4 * 512];
__device__ float g_h[2 * 256 * 128];
// CSR
__device__ int g_cnt[NMAX];
__device__ int g_off[NMAX + 1];
__device__ int g_cur[NMAX];
__device__ int g_bsum[64];
__device__ int g_boff[64];
__device__ uint32_t g_sed[EMAX];   // packed src | (r<<16)

// ---------------- bit-cast helpers ----------------
__device__ __forceinline__ uint32_t h2_as_u32(__half2 h) {
    uint32_t u; *(__half2*)&u = h; return u;
}
__device__ __forceinline__ __half2 u32_as_h2(uint32_t u) {
    __half2 h; *(uint32_t*)&h = u; return h;
}

// ---------------- PTX helpers ----------------
__device__ __forceinline__ uint32_t smem_u32(const void* p) {
    return (uint32_t)__cvta_generic_to_shared(p);
}
__device__ __forceinline__ void ldm_x4(uint32_t& r0, uint32_t& r1, uint32_t& r2, uint32_t& r3,
                                       uint32_t a) {
    asm volatile("ldmatrix.sync.aligned.m8n8.x4.shared.b16 {%0,%1,%2,%3}, [%4];"
                 : "=r"(r0), "=r"(r1), "=r"(r2), "=r"(r3) : "r"(a));
}
__device__ __forceinline__ void ldm_x2(uint32_t& r0, uint32_t& r1, uint32_t a) {
    asm volatile("ldmatrix.sync.aligned.m8n8.x2.shared.b16 {%0,%1}, [%2];"
                 : "=r"(r0), "=r"(r1) : "r"(a));
}
__device__ __forceinline__ void mma16816(float* c, uint32_t a0, uint32_t a1, uint32_t a2,
                                         uint32_t a3, uint32_t b0, uint32_t b1) {
    asm volatile(
        "mma.sync.aligned.m16n8k16.row.col.f32.f16.f16.f32 "
        "{%0,%1,%2,%3}, {%4,%5,%6,%7}, {%8,%9}, {%0,%1,%2,%3};"
        : "+f"(c[0]), "+f"(c[1]), "+f"(c[2]), "+f"(c[3])
        : "r"(a0), "r"(a1), "r"(a2), "r"(a3), "r"(b0), "r"(b1));
}
__device__ __forceinline__ void cpa16(uint32_t dst, const void* src) {
    asm volatile("cp.async.cg.shared.global [%0], [%1], 16;" :: "r"(dst), "l"(src));
}

// ---------------- CSR build ----------------
__global__ void k_zero_cnt(int N) {
    int i = blockIdx.x * blockDim.x + threadIdx.x;
    if (i < N) g_cnt[i] = 0;
}
__global__ void k_hist(const int* __restrict__ dst, int E) {
    int e = blockIdx.x * blockDim.x + threadIdx.x;
    if (e < E) atomicAdd(&g_cnt[dst[e]], 1);
}
// multi-block scan: 1024-elem blocks
__global__ __launch_bounds__(1024) void k_scan1(int N) {
    __shared__ int sh[1024];
    int i = blockIdx.x * 1024 + threadIdx.x;
    sh[threadIdx.x] = (i < N) ? g_cnt[i] : 0;
    __syncthreads();
    for (int o = 512; o > 0; o >>= 1) {
        if (threadIdx.x < o) sh[threadIdx.x] += sh[threadIdx.x + o];
        __syncthreads();
    }
    if (threadIdx.x == 0) g_bsum[blockIdx.x] = sh[0];
}
__global__ void k_scan2(int nb, int N) {
    __shared__ int sh[64];
    int t = threadIdx.x;   // 64 threads
    int v = (t < nb) ? g_bsum[t] : 0;
    sh[t] = v;
    __syncthreads();
    for (int o = 1; o < 64; o <<= 1) {
        int u = (t >= o) ? sh[t - o] : 0;
        __syncthreads();
        sh[t] += u;
        __syncthreads();
    }
    if (t < nb) g_boff[t] = sh[t] - v;
    if (t == nb - 1) g_off[N] = sh[t];
}
__global__ __launch_bounds__(1024) void k_scan3(int N) {
    __shared__ int sh[1024];
    int t = threadIdx.x;
    int i = blockIdx.x * 1024 + t;
    int v = (i < N) ? g_cnt[i] : 0;
    sh[t] = v;
    __syncthreads();
    for (int o = 1; o < 1024; o <<= 1) {
        int u = (t >= o) ? sh[t - o] : 0;
        __syncthreads();
        sh[t] += u;
        __syncthreads();
    }
    if (i < N) {
        int off = g_boff[blockIdx.x] + sh[t] - v;
        g_off[i] = off;
        g_cur[i] = off;
    }
}
__global__ void k_place(const int* __restrict__ src, const int* __restrict__ dst,
                        const int* __restrict__ et, int E) {
    int e = blockIdx.x * blockDim.x + threadIdx.x;
    if (e >= E) return;
    int pos = atomicAdd(&g_cur[dst[e]], 1);
    g_sed[pos] = (uint32_t)src[e] | ((uint32_t)et[e] << 16);
}

// ---------------- conversions ----------------
__global__ void k_conv(const float* __restrict__ x0, int Nn) {
    int i4 = blockIdx.x * blockDim.x + threadIdx.x;
    if (i4 >= MPAD * 32) return;
    int row = i4 >> 5;
    float4 v = make_float4(0.f, 0.f, 0.f, 0.f);
    if (row < Nn) v = *(const float4*)(x0 + (size_t)i4 * 4);
    __half2 h0 = __floats2half2_rn(v.x, v.y);
    __half2 h1 = __floats2half2_rn(v.z, v.w);
    float2 f0 = __half22float2(h0), f1 = __half22float2(h1);
    __half2 l0 = __floats2half2_rn(v.x - f0.x, v.y - f0.y);
    __half2 l1 = __floats2half2_rn(v.z - f1.x, v.w - f1.y);
    ((uint2*)g_Ah)[i4] = make_uint2(h2_as_u32(h0), h2_as_u32(h1));
    ((uint2*)g_Al)[i4] = make_uint2(h2_as_u32(l0), h2_as_u32(l1));
}

__global__ void k_packb(const float* __restrict__ Wrel, const float* __restrict__ Wself) {
    int idx0 = blockIdx.x * blockDim.x + threadIdx.x;
    if (idx0 >= 2 * NCOL * 128) return;
    int l = idx0 / (NCOL * 128);
    int idx = idx0 % (NCOL * 128);
    int n = idx >> 7, d = idx & 127;
    const float* Wr = Wrel + (size_t)l * R * 128 * 128;
    const float* Ws = Wself + (size_t)l * 128 * 128;
    float v;
    if (n < 2048) {
        int r = n >> 7, k = n & 127;
        v = Wr[((size_t)r * 128 + d) * 128 + k];
    } else {
        v = Ws[d * 128 + (n - 2048)];
    }
    g_Bh2[l][idx] = __float2half_rn(v);
}

// ---------------- shared GEMM helpers ----------------
__device__ __forceinline__ void load_tile(char* dstbase, const __half* g, int row0, int t) {
#pragma unroll
    for (int it = 0; it < 8; it++) {
        int cl = it * 256 + t;
        int row = cl >> 4, c = cl & 15;
        uint4 v = *(const uint4*)(g + (size_t)(row0 + row) * 128 + c * 8);
        *(uint4*)(dstbase + row * 256 + ((c ^ (row & 7)) * 16)) = v;
    }
}

__device__ __forceinline__ void prefetch_b(uint32_t dstb, const __half* gsrc, int t) {
#pragma unroll
    for (int it = 0; it < 8; it++) {
        int cl = it * 256 + t;
        int row = cl >> 4, c = cl & 15;
        cpa16(dstb + row * 256 + ((c ^ (row & 7)) * 16), gsrc + (size_t)row * 128 + c * 8);
    }
    asm volatile("cp.async.commit_group;");
}

// ---------------- unified GEMM: 17 n-tiles, single pass, 2 CTAs/SM ----------------
#define MM_AH 0
#define MM_B0 32768
#define MM_B1 65536
#define MSMEM 98304

__global__ __launch_bounds__(256, 2) void k_gemmM(int layer, int tbase) {
    extern __shared__ char smem[];
    int t = threadIdx.x, lane = t & 31, w = t >> 5;
    int m0 = (tbase + blockIdx.x) * 128;
    uint32_t sbase = smem_u32(smem);
    const __half* Bh = g_Bh2[layer];
    __half* trans = g_trans16[layer];
    float* selfp = g_self[layer];

    prefetch_b(sbase + MM_B0, Bh, t);
    load_tile(smem + MM_AH, g_Ah, m0, t);

    int wm = (w & 1) * 64, wn = (w >> 1) * 32;
    int atile = lane >> 3, ar = lane & 7;
    int arow_base = wm + ((atile & 1) << 3) + ar;
    int achunk_sel = atile >> 1;
    int bl = lane & 15;
    int bhalf = bl >> 3, br = bl & 7;

    for (int n = 0; n < 17; n++) {
        uint32_t boff = (n & 1) ? MM_B1 : MM_B0;
        uint32_t bbase = sbase + boff;
        asm volatile("cp.async.wait_group 0;");
        __syncthreads();
        if (n + 1 < 17) {
            prefetch_b(sbase + (((n + 1) & 1) ? MM_B1 : MM_B0),
                       Bh + (size_t)(n + 1) * 128 * 128, t);
        }

        float acc[4][4][4];
#pragma unroll
        for (int i = 0; i < 4; i++)
#pragma unroll
            for (int j = 0; j < 4; j++)
#pragma unroll
                for (int q = 0; q < 4; q++) acc[i][j][q] = 0.0f;

#pragma unroll
        for (int ks = 0; ks < 8; ks++) {
            uint32_t a[4][4];
            uint32_t b[4][2];
            int ac = ks * 2 + achunk_sel;
#pragma unroll
            for (int i = 0; i < 4; i++) {
                int row = arow_base + i * 16;
                ldm_x4(a[i][0], a[i][1], a[i][2], a[i][3],
                       sbase + MM_AH + row * 256 + ((ac ^ (row & 7)) * 16));
            }
            int bc = ks * 2 + bhalf;
#pragma unroll
            for (int j = 0; j < 4; j++) {
                int row = wn + j * 8 + br;
                ldm_x2(b[j][0], b[j][1], bbase + row * 256 + ((bc ^ (row & 7)) * 16));
            }
#pragma unroll
            for (int i = 0; i < 4; i++)
#pragma unroll
                for (int j = 0; j < 4; j++)
                    mma16816(acc[i][j], a[i][0], a[i][1], a[i][2], a[i][3], b[j][0], b[j][1]);
        }

        if (n < 16) {
            __syncthreads();
            char* cs = smem + boff;
#pragma unroll
            for (int i = 0; i < 4; i++) {
#pragma unroll
                for (int j = 0; j < 4; j++) {
                    int r = wm + i * 16 + (lane >> 2);
                    int cb = (wn + j * 8 + 2 * (lane & 3)) * 2;
                    uint32_t off0 = r * 256 + ((((cb >> 4) ^ (r & 7)) << 4) | (cb & 15));
                    uint32_t off1 = (r + 8) * 256 + ((((cb >> 4) ^ ((r + 8) & 7)) << 4) | (cb & 15));
                    *(__half2*)(cs + off0) = __floats2half2_rn(acc[i][j][0], acc[i][j][1]);
                    *(__half2*)(cs + off1) = __floats2half2_rn(acc[i][j][2], acc[i][j][3]);
                }
            }
            __syncthreads();
#pragma unroll
            for (int it = 0; it < 8; it++) {
                int idx = it * 256 + t;
                int row = idx >> 4, ch = idx & 15;
                uint4 v = *(const uint4*)(cs + row * 256 + ((ch ^ (row & 7)) << 4));
                *(uint4*)(trans + (size_t)(m0 + row) * 2048 + n * 128 + ch * 8) = v;
            }
            __syncthreads();
        } else {
#pragma unroll
            for (int i = 0; i < 4; i++) {
#pragma unroll
                for (int j = 0; j < 4; j++) {
                    int r = wm + i * 16 + (lane >> 2);
                    int c = wn + j * 8 + 2 * (lane & 3);
                    *(float2*)(selfp + (size_t)(m0 + r) * 128 + c) =
                        make_float2(acc[i][j][0], acc[i][j][1]);
                    *(float2*)(selfp + (size_t)(m0 + r + 8) * 128 + c) =
                        make_float2(acc[i][j][2], acc[i][j][3]);
                }
            }
        }
    }
}

// ---------------- fused gather + update ----------------
__device__ __forceinline__ void acc8(float* a, uint4 r) {
    float2 f;
    f = __half22float2(u32_as_h2(r.x)); a[0] += f.x; a[1] += f.y;
    f = __half22float2(u32_as_h2(r.y)); a[2] += f.x; a[3] += f.y;
    f = __half22float2(u32_as_h2(r.z)); a[4] += f.x; a[5] += f.y;
    f = __half22float2(u32_as_h2(r.w)); a[6] += f.x; a[7] += f.y;
}
__device__ __forceinline__ uint4 ldg_msg(const __half* p) {
    return __ldg((const uint4*)p);
}

__global__ __launch_bounds__(256) void k_gather(const float* __restrict__ bself,
                                                const float* __restrict__ lg,
                                                const float* __restrict__ lb,
                                                float* __restrict__ enc_out,
                                                int layer, int nbase, int nend) {
    int n = nbase + blockIdx.x * 8 + (threadIdx.x >> 5);
    int lane = threadIdx.x & 31;
    if (n >= nend) return;
    int half = lane >> 4, hl = lane & 15;
    int beg = g_off[n], end = g_off[n + 1];
    const __half* trans = g_trans16[layer];
    const float* selfp = g_self[layer];

    float acc[8];
#pragma unroll
    for (int q = 0; q < 8; q++) acc[q] = 0.0f;

    int e = beg + half;
    for (; e + 6 < end; e += 8) {
        uint32_t p0 = g_sed[e], p1 = g_sed[e + 2], p2 = g_sed[e + 4], p3 = g_sed[e + 6];
        uint4 r0 = ldg_msg(trans + (size_t)(p0 & 0xFFFF) * 2048 + ((p0 >> 16) << 7) + hl * 8);
        uint4 r1 = ldg_msg(trans + (size_t)(p1 & 0xFFFF) * 2048 + ((p1 >> 16) << 7) + hl * 8);
        uint4 r2 = ldg_msg(trans + (size_t)(p2 & 0xFFFF) * 2048 + ((p2 >> 16) << 7) + hl * 8);
        uint4 r3 = ldg_msg(trans + (size_t)(p3 & 0xFFFF) * 2048 + ((p3 >> 16) << 7) + hl * 8);
        acc8(acc, r0); acc8(acc, r1); acc8(acc, r2); acc8(acc, r3);
    }
    for (; e < end; e += 2) {
        uint32_t p = g_sed[e];
        uint4 r = ldg_msg(trans + (size_t)(p & 0xFFFF) * 2048 + ((p >> 16) << 7) + hl * 8);
        acc8(acc, r);
    }
#pragma unroll
    for (int q = 0; q < 8; q++) acc[q] += __shfl_xor_sync(0xFFFFFFFFu, acc[q], 16);

    float inv = 1.0f / fmaxf((float)(end - beg), 1.0f);
    float4 s0 = *(const float4*)(selfp + (size_t)n * 128 + hl * 8);
    float4 s1 = *(const float4*)(selfp + (size_t)n * 128 + hl * 8 + 4);
    float4 b0 = *(const float4*)(bself + hl * 8);
    float4 b1 = *(const float4*)(bself + hl * 8 + 4);
    float v[8];
    v[0] = fmaxf(s0.x + b0.x + acc[0] * inv, 0.f);
    v[1] = fmaxf(s0.y + b0.y + acc[1] * inv, 0.f);
    v[2] = fmaxf(s0.z + b0.z + acc[2] * inv, 0.f);
    v[3] = fmaxf(s0.w + b0.w + acc[3] * inv, 0.f);
    v[4] = fmaxf(s1.x + b1.x + acc[4] * inv, 0.f);
    v[5] = fmaxf(s1.y + b1.y + acc[5] * inv, 0.f);
    v[6] = fmaxf(s1.z + b1.z + acc[6] * inv, 0.f);
    v[7] = fmaxf(s1.w + b1.w + acc[7] * inv, 0.f);

    float s = 0.f;
#pragma unroll
    for (int q = 0; q < 8; q++) s += v[q];
#pragma unroll
    for (int o = 1; o < 16; o <<= 1) s += __shfl_xor_sync(0xFFFFFFFFu, s, o);
    float mu = s * (1.0f / 128.0f);
    float qs = 0.f;
    float dv[8];
#pragma unroll
    for (int q = 0; q < 8; q++) { dv[q] = v[q] - mu; qs += dv[q] * dv[q]; }
#pragma unroll
    for (int o = 1; o < 16; o <<= 1) qs += __shfl_xor_sync(0xFFFFFFFFu, qs, o);
    float rstd = rsqrtf(qs * (1.0f / 128.0f) + 1e-5f);

    float4 g0 = *(const float4*)(lg + hl * 8);
    float4 g1 = *(const float4*)(lg + hl * 8 + 4);
    float4 p0 = *(const float4*)(lb + hl * 8);
    float4 p1 = *(const float4*)(lb + hl * 8 + 4);
    float ov[8];
    ov[0] = dv[0] * rstd * g0.x + p0.x; ov[1] = dv[1] * rstd * g0.y + p0.y;
    ov[2] = dv[2] * rstd * g0.z + p0.z; ov[3] = dv[3] * rstd * g0.w + p0.w;
    ov[4] = dv[4] * rstd * g1.x + p1.x; ov[5] = dv[5] * rstd * g1.y + p1.y;
    ov[6] = dv[6] * rstd * g1.z + p1.z; ov[7] = dv[7] * rstd * g1.w + p1.w;

    if (half == 0) {
        if (layer == 0) {
            __half2 h0 = __floats2half2_rn(ov[0], ov[1]);
            __half2 h1 = __floats2half2_rn(ov[2], ov[3]);
            __half2 h2 = __floats2half2_rn(ov[4], ov[5]);
            __half2 h3 = __floats2half2_rn(ov[6], ov[7]);
            float2 f0 = __half22float2(h0), f1 = __half22float2(h1);
            float2 f2 = __half22float2(h2), f3 = __half22float2(h3);
            __half2 l0 = __floats2half2_rn(ov[0] - f0.x, ov[1] - f0.y);
            __half2 l1 = __floats2half2_rn(ov[2] - f1.x, ov[3] - f1.y);
            __half2 l2 = __floats2half2_rn(ov[4] - f2.x, ov[5] - f2.y);
            __half2 l3 = __floats2half2_rn(ov[6] - f3.x, ov[7] - f3.y);
            *(uint4*)(g_Ah + (size_t)n * 128 + hl * 8) =
                make_uint4(h2_as_u32(h0), h2_as_u32(h1), h2_as_u32(h2), h2_as_u32(h3));
            *(uint4*)(g_Al + (size_t)n * 128 + hl * 8) =
                make_uint4(h2_as_u32(l0), h2_as_u32(l1), h2_as_u32(l2), h2_as_u32(l3));
        } else {
            *(float4*)(enc_out + (size_t)n * 128 + hl * 8) =
                make_float4(ov[0], ov[1], ov[2], ov[3]);
            *(float4*)(enc_out + (size_t)n * 128 + hl * 8 + 4) =
                make_float4(ov[4], ov[5], ov[6], ov[7]);
        }
    }
}

__global__ void k_wt(const float* __restrict__ Wih_f, const float* __restrict__ Whh_f,
                     const float* __restrict__ Wih_b, const float* __restrict__ Whh_b) {
    int idx = blockIdx.x * blockDim.x + threadIdx.x;
    if (idx >= 2 * 384 * 512) return;
    int dir = idx / (384 * 512);
    int rem = idx % (384 * 512);
    int d = rem / 512, j = rem % 512;
    const float* Wih = dir ? Wih_b : Wih_f;
    const float* Whh = dir ? Whh_b : Whh_f;
    float v = (d < 256) ? Wih[j * 256 + d] : Whh[j * 128 + (d - 256)];
    g_WT[dir][rem] = v;
}

// ---------------- LSTM input projection (seq build fused in) ----------------
__global__ __launch_bounds__(512) void k_xgate(const float* __restrict__ enc,
                                               const int* __restrict__ pn,
                                               const int* __restrict__ pr,
                                               const float* __restrict__ rel,
                                               const float* __restrict__ bf,
                                               const float* __restrict__ bb) {
    __shared__ float xt[256];
    int pl = blockIdx.x;
    int p = pl >> 2, tt = pl & 3;
    int dir = blockIdx.y;
    int j = threadIdx.x;
    const float* WT = g_WT[dir];
    const float* bias = dir ? bb : bf;
    if (j < 128) {
        int node = pn[p * 4 + tt];
        xt[j] = enc[(size_t)node * 128 + j];
    } else if (j < 256) {
        int d = j - 128;
        float rv = 0.0f;
        if (tt > 0) { int r = pr[p * 3 + (tt - 1)]; rv = rel[r * 128 + d]; }
        xt[j] = rv;
    }
    __syncthreads();
    float acc = bias[j];
    for (int d = 0; d < 256; d++) acc = fmaf(WT[d * 512 + j], xt[d], acc);
    g_gx[((size_t)dir * 1024 + pl) * 512 + j] = acc;
}

// ---------------- bidirectional LSTM: recurrent part only ----------------
__global__ __launch_bounds__(512) void k_lstm() {
    const int PB = 8;
    __shared__ float hs[PB][128];
    __shared__ float cs[PB][128];
    __shared__ float gs[PB][512];
    int dir = blockIdx.y;
    const float* WT = g_WT[dir];
    int p0 = blockIdx.x * PB;
    int t = threadIdx.x;

    for (int i = t; i < PB * 128; i += 512) { ((float*)hs)[i] = 0.0f; ((float*)cs)[i] = 0.0f; }
    __syncthreads();

    for (int step = 0; step < 4; step++) {
        int tt = dir ? (3 - step) : step;
        float acc[PB];
#pragma unroll
        for (int p = 0; p < PB; p++)
            acc[p] = g_gx[((size_t)dir * 1024 + (p0 + p) * 4 + tt) * 512 + t];
        for (int d = 0; d < 128; d++) {
            float w = WT[(256 + d) * 512 + t];
#pragma unroll
            for (int p = 0; p < PB; p++) acc[p] = fmaf(w, hs[p][d], acc[p]);
        }
#pragma unroll
        for (int p = 0; p < PB; p++) gs[p][t] = acc[p];
        __syncthreads();
        for (int i = t; i < PB * 128; i += 512) {
            int pp = i >> 7, k = i & 127;
            float ig = 1.0f / (1.0f + expf(-gs[pp][k]));
            float fg = 1.0f / (1.0f + expf(-gs[pp][128 + k]));
            float gg = tanhf(gs[pp][256 + k]);
            float og = 1.0f / (1.0f + expf(-gs[pp][384 + k]));
            float c = fg * cs[pp][k] + ig * gg;
            cs[pp][k] = c;
            hs[pp][k] = og * tanhf(c);
        }
        __syncthreads();
    }
    for (int i = t; i < PB * 128; i += 512) {
        int pp = i >> 7, k = i & 127;
        g_h[((size_t)dir * 256 + p0 + pp) * 128 + k] = hs[pp][k];
    }
}

// ---------------- output head ----------------
__global__ void k_head(const float* __restrict__ Wop, const float* __restrict__ bop,
                       const float* __restrict__ q, const float* __restrict__ Ws1,
                       const float* __restrict__ bs1, const float* __restrict__ Ws2,
                       const float* __restrict__ bs2,
                       float* __restrict__ pe_out, float* __restrict__ sim_out) {
    int p = blockIdx.x;
    int k = threadIdx.x;
    __shared__ float cat[256];
    __shared__ float cat2[256];
    __shared__ float red[4];
    cat[k]       = g_h[(size_t)p * 128 + k];
    cat[128 + k] = g_h[(size_t)(256 + p) * 128 + k];
    __syncthreads();
    float acc = bop[k];
    for (int j = 0; j < 256; j++) acc = fmaf(cat[j], Wop[k * 256 + j], acc);
    float pe = fmaxf(acc, 0.0f);
    pe_out[(size_t)p * 128 + k] = pe;
    cat2[k] = pe;
    cat2[128 + k] = q[k];
    __syncthreads();
    float a2 = bs1[k];
    for (int j = 0; j < 256; j++) a2 = fmaf(cat2[j], Ws1[k * 256 + j], a2);
    float hdn = fmaxf(a2, 0.0f);
    float s = hdn * Ws2[k];
#pragma unroll
    for (int o = 16; o > 0; o >>= 1) s += __shfl_xor_sync(0xFFFFFFFFu, s, o);
    if ((k & 31) == 0) red[k >> 5] = s;
    __syncthreads();
    if (k == 0) {
        float tot = red[0] + red[1] + red[2] + red[3] + bs2[0];
        sim_out[p] = 1.0f / (1.0f + expf(-tot));
    }
}

// ---------------- launch ----------------
extern "C" void kernel_launch(void* const* d_in, const int* in_sizes, int n_in,
                              void* d_out, int out_size) {
    const float* node_features = (const float*)d_in[0];
    const int*   edge_index    = (const int*)d_in[1];
    const int*   edge_types    = (const int*)d_in[2];
    const float* query         = (const float*)d_in[3];
    const int*   path_nodes    = (const int*)d_in[4];
    const int*   path_rel      = (const int*)d_in[5];
    const float* W_self        = (const float*)d_in[6];
    const float* b_self        = (const float*)d_in[7];
    const float* W_rel         = (const float*)d_in[8];
    const float* ln_g          = (const float*)d_in[9];
    const float* ln_b          = (const float*)d_in[10];
    const float* rel_emb       = (const float*)d_in[11];
    const float* W_ih_f        = (const float*)d_in[12];
    const float* W_hh_f        = (const float*)d_in[13];
    const float* b_f           = (const float*)d_in[14];
    const float* W_ih_b        = (const float*)d_in[15];
    const float* W_hh_b        = (const float*)d_in[16];
    const float* b_b           = (const float*)d_in[17];
    const float* W_op          = (const float*)d_in[18];
    const float* b_op          = (const float*)d_in[19];
    const float* W_s1          = (const float*)d_in[20];
    const float* b_s1          = (const float*)d_in[21];
    const float* W_s2          = (const float*)d_in[22];
    const float* b_s2          = (const float*)d_in[23];
    (void)n_in; (void)out_size;

    const int N = in_sizes[0] / 128;
    const int E = in_sizes[1] / 2;
    const int P = in_sizes[4] / 4;

    float* out     = (float*)d_out;
    float* enc_out = out;
    float* pe_out  = out + (size_t)N * 128;
    float* sim_out = pe_out + (size_t)P * 128;

    const int* src = edge_index;
    const int* dst = edge_index + E;

    static cudaStream_t s1 = nullptr;
    static cudaEvent_t e0 = nullptr, e1 = nullptr, e2 = nullptr,
                       eL = nullptr, eH = nullptr, e3 = nullptr;
    if (s1 == nullptr) {
        cudaStreamCreateWithFlags(&s1, cudaStreamNonBlocking);
        cudaEventCreateWithFlags(&e0, cudaEventDisableTiming);
        cudaEventCreateWithFlags(&e1, cudaEventDisableTiming);
        cudaEventCreateWithFlags(&e2, cudaEventDisableTiming);
        cudaEventCreateWithFlags(&eL, cudaEventDisableTiming);
        cudaEventCreateWithFlags(&eH, cudaEventDisableTiming);
        cudaEventCreateWithFlags(&e3, cudaEventDisableTiming);
        cudaFuncSetAttribute(k_gemmM, cudaFuncAttributeMaxDynamicSharedMemorySize, MSMEM);
    }

    const int nb = (N + 1023) / 1024;   // scan blocks

    // fork: side stream does weight packing + CSR build + LSTM weight transpose
    cudaEventRecord(e0, 0);
    cudaStreamWaitEvent(s1, e0, 0);
    k_packb<<<(2 * NCOL * 128 + 255) / 256, 256, 0, s1>>>(W_rel, W_self);
    cudaEventRecord(e1, s1);
    k_zero_cnt<<<(N + 255) / 256, 256, 0, s1>>>(N);
    k_hist<<<(E + 255) / 256, 256, 0, s1>>>(dst, E);
    k_scan1<<<nb, 1024, 0, s1>>>(N);
    k_scan2<<<1, 64, 0, s1>>>(nb, N);
    k_scan3<<<nb, 1024, 0, s1>>>(N);
    k_place<<<(E + 255) / 256, 256, 0, s1>>>(src, dst, edge_types, E);
    k_wt<<<(2 * 384 * 512 + 255) / 256, 256, 0, s1>>>(W_ih_f, W_hh_f, W_ih_b, W_hh_b);
    cudaEventRecord(e2, s1);

    // main: layer 0
    k_conv<<<(MPAD * 32 + 255) / 256, 256>>>(node_features, N);
    cudaStreamWaitEvent(0, e1, 0);
    k_gemmM<<<MPAD / 128, 256, MSMEM>>>(0, 0);
    cudaStreamWaitEvent(0, e2, 0);
    k_gather<<<HSPLIT / 8, 256>>>(b_self, ln_g, ln_b, enc_out, 0, 0, HSPLIT);
    cudaEventRecord(eL, 0);
    k_gather<<<(N - HSPLIT + 7) / 8, 256>>>(b_self, ln_g, ln_b, enc_out, 0, HSPLIT, N);
    cudaEventRecord(eH, 0);

    // layer-1 GEMM pipelined against gather0 on side stream
    cudaStreamWaitEvent(s1, eL, 0);
    k_gemmM<<<HSPLIT / 128, 256, MSMEM, s1>>>(1, 0);
    cudaStreamWaitEvent(s1, eH, 0);
    k_gemmM<<<(MPAD - HSPLIT) / 128, 256, MSMEM, s1>>>(1, HSPLIT / 128);
    cudaEventRecord(e3, s1);

    // main: layer-1 gather + path encoder
    cudaStreamWaitEvent(0, e3, 0);
    k_gather<<<(N + 7) / 8, 256>>>(b_self + 128, ln_g + 128, ln_b + 128, enc_out, 1, 0, N);
    k_xgate<<<dim3(P * 4, 2), 512>>>(enc_out, path_nodes, path_rel, rel_emb, b_f, b_b);
    k_lstm<<<dim3(P / 8, 2), 512>>>();
    k_head<<<P, 128>>>(W_op, b_op, query, W_s1, b_s1, W_s2, b_s2, pe_out, sim_out);
}